// round 13
// baseline (speedup 1.0000x reference)
#include <cuda_runtime.h>
#include <cuda_bf16.h>
#include <math.h>
#include <stdint.h>

#define NN 50000
#define NE 800000

typedef __nv_bfloat16 bf16;

// ---------------- scratch (device globals) ----------------
__device__ __align__(16) bf16 g_xh[NN * 128], g_xl[NN * 128];
__device__ __align__(16) bf16 g_gxh[NN * 128], g_gxl[NN * 128];
__device__ float g_hr[NN * 512];                          // [res | h] fused layer out
__device__ __align__(16) bf16 g_z1h[NN * 256], g_z1l[NN * 256];
__device__ __align__(16) bf16 g_z2h[NN * 256], g_z2l[NN * 256];
__device__ __align__(16) bf16 g_t64h[NN * 64], g_t64l[NN * 64];
__device__ float g_zself[NN * 64];
__device__ float g_h3[NN * 64];
__device__ float g_asrc[NN * 4];
__device__ float g_adst[NN * 4];
__device__ float g_loop[NN];
__device__ float g_easum[NN];
__device__ int   g_deg[NN];
__device__ int   g_rowstart[NN];
__device__ int   g_cursor[NN];
__device__ int   g_csr[NE];
__device__ float g_ch[4];
__device__ int   g_total;
// transposed [n][k] k-major bf16 weight splits
__device__ __align__(16) bf16 g_wfa_h[128 * 128], g_wfa_l[128 * 128];
__device__ __align__(16) bf16 g_wb1_h[512 * 128], g_wb1_l[512 * 128];
__device__ __align__(16) bf16 g_wb2_h[512 * 256], g_wb2_l[512 * 256];
__device__ __align__(16) bf16 g_w3_h[64 * 256],  g_w3_l[64 * 256];
__device__ __align__(16) bf16 g_wf1_h[64 * 128], g_wf1_l[64 * 128];
__device__ __align__(16) bf16 g_wf2_h[64 * 64],  g_wf2_l[64 * 64];
__device__ float g_bb1[512], g_bb2[512];

__device__ __forceinline__ float sigf(float x) { return 1.f / (1.f + __expf(-x)); }

__device__ __forceinline__ void bf_split(float x, bf16& h, bf16& l) {
    h = __float2bfloat16(x);
    l = __float2bfloat16(x - __bfloat162float(h));
}

__device__ __forceinline__ void mma_bf16(float* c, const uint32_t* a, const uint32_t* b) {
    asm volatile(
        "mma.sync.aligned.m16n8k16.row.col.f32.bf16.bf16.f32 "
        "{%0,%1,%2,%3}, {%4,%5,%6,%7}, {%8,%9}, {%0,%1,%2,%3};\n"
        : "+f"(c[0]), "+f"(c[1]), "+f"(c[2]), "+f"(c[3])
        : "r"(a[0]), "r"(a[1]), "r"(a[2]), "r"(a[3]), "r"(b[0]), "r"(b[1]));
}

__device__ __forceinline__ void ldsm_x4(uint32_t& r0, uint32_t& r1, uint32_t& r2,
                                        uint32_t& r3, uint32_t addr) {
    asm volatile("ldmatrix.sync.aligned.m8n8.x4.shared.b16 {%0,%1,%2,%3}, [%4];"
                 : "=r"(r0), "=r"(r1), "=r"(r2), "=r"(r3) : "r"(addr));
}

__device__ __forceinline__ void cp16(uint32_t dst, const void* src, int sz) {
    asm volatile("cp.async.cg.shared.global [%0], [%1], 16, %2;\n"
                 :: "r"(dst), "l"(src), "r"(sz));
}
__device__ __forceinline__ void cp_commit() {
    asm volatile("cp.async.commit_group;\n");
}
template <int N>
__device__ __forceinline__ void cp_wait() {
    asm volatile("cp.async.wait_group %0;\n" :: "n"(N));
}

// ---------------- pack / split kernels ----------------
__global__ void split_bf_kernel(const float* __restrict__ s, bf16* __restrict__ dh,
                                bf16* __restrict__ dl, int n) {
    int i = blockIdx.x * blockDim.x + threadIdx.x;
    if (i < n) { bf16 h, l; bf_split(s[i], h, l); dh[i] = h; dl[i] = l; }
}
__global__ void packall_kernel(const float* __restrict__ fa_w,
                               const float* __restrict__ r1_w, const float* __restrict__ W1,
                               const float* __restrict__ r1_b, const float* __restrict__ r2_b) {
    int i = blockIdx.x * blockDim.x + threadIdx.x;
    if (i < 16384) {
        int n = i >> 7, k = i & 127;
        bf16 h, l; bf_split(fa_w[k * 128 + n], h, l);
        g_wfa_h[i] = h; g_wfa_l[i] = l;
    } else if (i < 16384 + 65536) {
        int j = i - 16384;
        int n = j >> 7, k = j & 127;
        float v = (n < 256) ? r1_w[k * 256 + n] : W1[k * 256 + n - 256];
        bf16 h, l; bf_split(v, h, l);
        g_wb1_h[j] = h; g_wb1_l[j] = l;
    } else if (i < 16384 + 65536 + 512) {
        int j = i - 81920;
        g_bb1[j] = (j < 256) ? r1_b[j] : 0.f;
    } else if (i < 16384 + 65536 + 1024) {
        int j = i - 82432;
        g_bb2[j] = (j < 256) ? r2_b[j] : 0.f;
    }
}
__global__ void packT_kernel(const float* __restrict__ W, bf16* __restrict__ th,
                             bf16* __restrict__ tl, int K_, int N_) {
    int i = blockIdx.x * blockDim.x + threadIdx.x;
    if (i < K_ * N_) {
        int n = i / K_, k = i % K_;
        bf16 h, l; bf_split(W[k * N_ + n], h, l);
        th[i] = h; tl[i] = l;
    }
}
__global__ void packfuseT_kernel(const float* __restrict__ A_, const float* __restrict__ B_,
                                 bf16* __restrict__ th, bf16* __restrict__ tl,
                                 int K_, int half) {
    int i = blockIdx.x * blockDim.x + threadIdx.x;
    if (i < 2 * half * K_) {
        int n = i / K_, k = i % K_;
        float v = (n < half) ? A_[k * half + n] : B_[k * half + n - half];
        bf16 h, l; bf_split(v, h, l);
        th[i] = h; tl[i] = l;
    }
}

#define EP_NONE 0
#define EP_GATE 1
#define EP_RELU 2

// ---------------- gemm5: bf16x3 m16n8k16, BM=128 BN=64 BK=32 (N=64 cases) --
#define SMEM_DB (15360 * 4)

template <int EP, bool SPLITOUT, bool WRITEC>
__global__ __launch_bounds__(256) void gemm5(
    const bf16* __restrict__ Agh, const bf16* __restrict__ Agl,
    const bf16* __restrict__ Bgh, const bf16* __restrict__ Bgl,
    const float* __restrict__ bias, const float* __restrict__ gateA,
    float* __restrict__ C, bf16* __restrict__ Ch, bf16* __restrict__ Cl,
    int M, int K, int N) {
    extern __shared__ uint32_t smu[];
    const int bm = blockIdx.y * 128, bn = blockIdx.x * 64;
    const int tid = threadIdx.x, lane = tid & 31, wid = tid >> 5;
    const int wm = wid >> 1, wn = wid & 1;
    const int lg = lane >> 2, lt = lane & 3;
    const int arow = tid >> 2, q = tid & 3;

    float acc[2][4][4];
#pragma unroll
    for (int mt = 0; mt < 2; mt++)
#pragma unroll
        for (int nt = 0; nt < 4; nt++)
#pragma unroll
            for (int j = 0; j < 4; j++) acc[mt][nt][j] = 0.f;

    uint4 rA[2][2], rB[2];
    const uint4 z16 = make_uint4(0u, 0u, 0u, 0u);

#pragma unroll
    for (int t = 0; t < 2; t++) {
        int grow = bm + arow + t * 64;
        if (grow < M) {
            rA[t][0] = ((const uint4*)(Agh + (size_t)grow * K))[q];
            rA[t][1] = ((const uint4*)(Agl + (size_t)grow * K))[q];
        } else { rA[t][0] = z16; rA[t][1] = z16; }
    }
    rB[0] = ((const uint4*)(Bgh + (size_t)(bn + arow) * K))[q];
    rB[1] = ((const uint4*)(Bgl + (size_t)(bn + arow) * K))[q];

    int p = 0;
    {
#pragma unroll
        for (int t = 0; t < 2; t++) {
            int row = arow + t * 64;
#pragma unroll
            for (int s = 0; s < 2; s++) {
                uint32_t* d = smu + s * 2560 + row * 20 + q * 4;
                uint4 v = rA[t][s];
                d[0] = v.x; d[1] = v.y; d[2] = v.z; d[3] = v.w;
            }
        }
#pragma unroll
        for (int s = 0; s < 2; s++) {
            uint32_t* d = smu + 10240 + s * 1280 + arow * 20 + q * 4;
            uint4 v = rB[s];
            d[0] = v.x; d[1] = v.y; d[2] = v.z; d[3] = v.w;
        }
    }
    __syncthreads();

    for (int k0 = 0; k0 < K; k0 += 32) {
        const bool more = (k0 + 32 < K);
        if (more) {
            int kn = k0 + 32;
#pragma unroll
            for (int t = 0; t < 2; t++) {
                int grow = bm + arow + t * 64;
                if (grow < M) {
                    rA[t][0] = ((const uint4*)(Agh + (size_t)grow * K + kn))[q];
                    rA[t][1] = ((const uint4*)(Agl + (size_t)grow * K + kn))[q];
                } else { rA[t][0] = z16; rA[t][1] = z16; }
            }
            rB[0] = ((const uint4*)(Bgh + (size_t)(bn + arow) * K + kn))[q];
            rB[1] = ((const uint4*)(Bgl + (size_t)(bn + arow) * K + kn))[q];
        }
        {
            const uint32_t* Ah = smu + (p * 2 + 0) * 2560;
            const uint32_t* Al = smu + (p * 2 + 1) * 2560;
            const uint32_t* Bh = smu + 10240 + (p * 2 + 0) * 1280;
            const uint32_t* Bl = smu + 10240 + (p * 2 + 1) * 1280;
#pragma unroll
            for (int ks = 0; ks < 2; ks++) {
                const int kp = ks * 8 + lt;
                uint32_t ah[2][4], al[2][4];
#pragma unroll
                for (int mt = 0; mt < 2; mt++) {
                    int r = wm * 32 + mt * 16 + lg;
                    ah[mt][0] = Ah[r * 20 + kp];
                    ah[mt][1] = Ah[(r + 8) * 20 + kp];
                    ah[mt][2] = Ah[r * 20 + kp + 4];
                    ah[mt][3] = Ah[(r + 8) * 20 + kp + 4];
                    al[mt][0] = Al[r * 20 + kp];
                    al[mt][1] = Al[(r + 8) * 20 + kp];
                    al[mt][2] = Al[r * 20 + kp + 4];
                    al[mt][3] = Al[(r + 8) * 20 + kp + 4];
                }
#pragma unroll
                for (int nt = 0; nt < 4; nt++) {
                    int c = wn * 32 + nt * 8 + lg;
                    uint32_t bh[2], bl2[2];
                    bh[0] = Bh[c * 20 + kp];
                    bh[1] = Bh[c * 20 + kp + 4];
                    bl2[0] = Bl[c * 20 + kp];
                    bl2[1] = Bl[c * 20 + kp + 4];
#pragma unroll
                    for (int mt = 0; mt < 2; mt++) {
                        mma_bf16(acc[mt][nt], ah[mt], bh);
                        mma_bf16(acc[mt][nt], al[mt], bh);
                        mma_bf16(acc[mt][nt], ah[mt], bl2);
                    }
                }
            }
        }
        if (more) {
            int pb = p ^ 1;
#pragma unroll
            for (int t = 0; t < 2; t++) {
                int row = arow + t * 64;
#pragma unroll
                for (int s = 0; s < 2; s++) {
                    uint32_t* d = smu + (pb * 2 + s) * 2560 + row * 20 + q * 4;
                    uint4 v = rA[t][s];
                    d[0] = v.x; d[1] = v.y; d[2] = v.z; d[3] = v.w;
                }
            }
#pragma unroll
            for (int s = 0; s < 2; s++) {
                uint32_t* d = smu + 10240 + (pb * 2 + s) * 1280 + arow * 20 + q * 4;
                uint4 v = rB[s];
                d[0] = v.x; d[1] = v.y; d[2] = v.z; d[3] = v.w;
            }
            __syncthreads();
            p = pb;
        }
    }
#pragma unroll
    for (int mt = 0; mt < 2; mt++) {
        int r0 = bm + wm * 32 + mt * 16 + lg;
#pragma unroll
        for (int nt = 0; nt < 4; nt++) {
            int c0 = bn + wn * 32 + nt * 8 + lt * 2;
#pragma unroll
            for (int j = 0; j < 4; j++) {
                int row = r0 + (j >> 1) * 8;
                int col = c0 + (j & 1);
                if (row >= M) continue;
                float v = acc[mt][nt][j] + (bias ? bias[col] : 0.f);
                if (EP == EP_GATE) v = gateA[(size_t)row * K + col] * sigf(v);
                else if (EP == EP_RELU) v = fmaxf(v, 0.f);
                size_t idx = (size_t)row * N + col;
                if (WRITEC) C[idx] = v;
                if (SPLITOUT) {
                    bf16 h, l; bf_split(v, h, l);
                    Ch[idx] = h; Cl[idx] = l;
                }
            }
        }
    }
}

// ---------------- gemm6: BM=128 BN=128, 4 warps 64x64, cp.async + ldmatrix --
#define SMEM2 (20480 * 4)

template <int EP, bool SPLITOUT, bool WRITEC>
__global__ __launch_bounds__(128) void gemm6(
    const bf16* __restrict__ Agh, const bf16* __restrict__ Agl,
    const bf16* __restrict__ Bgh, const bf16* __restrict__ Bgl,
    const float* __restrict__ bias, const float* __restrict__ gateA,
    float* __restrict__ C, bf16* __restrict__ Ch, bf16* __restrict__ Cl,
    int M, int K, int N) {
    extern __shared__ uint32_t smu[];
    const int bm = blockIdx.y * 128, bn = blockIdx.x * 128;
    const int tid = threadIdx.x, lane = tid & 31, wid = tid >> 5;
    const int wm = wid >> 1, wn = wid & 1;
    const int lg = lane >> 2, lt = lane & 3;
    const uint32_t smb = (uint32_t)__cvta_generic_to_shared(smu);

    const int lane7 = lane & 7;
    const int aoff = (wm * 64 + lane7 + ((lane >> 3) & 1) * 8) * 20 + ((lane >> 4) & 1) * 4;
    const int boff = (wn * 64 + lane7 + ((lane >> 4) & 1) * 8) * 20 + ((lane >> 3) & 1) * 4;

    float acc[4][8][4];
#pragma unroll
    for (int mt = 0; mt < 4; mt++)
#pragma unroll
        for (int nt = 0; nt < 8; nt++)
#pragma unroll
            for (int j = 0; j < 4; j++) acc[mt][nt][j] = 0.f;

    auto issue = [&](int p, int k0) {
#pragma unroll
        for (int i = 0; i < 4; i++) {
            int idx = tid + i * 128;
            int row = idx >> 2, q = idx & 3;
            int grow = bm + row;
            int sz = (grow < M) ? 16 : 0;
            int cg = (grow < M) ? grow : (M - 1);
            cp16(smb + (((p * 2 + 0) * 2560 + row * 20 + q * 4) << 2),
                 Agh + (size_t)cg * K + k0 + q * 8, sz);
            cp16(smb + (((p * 2 + 1) * 2560 + row * 20 + q * 4) << 2),
                 Agl + (size_t)cg * K + k0 + q * 8, sz);
            cp16(smb + ((10240 + (p * 2 + 0) * 2560 + row * 20 + q * 4) << 2),
                 Bgh + (size_t)(bn + row) * K + k0 + q * 8, 16);
            cp16(smb + ((10240 + (p * 2 + 1) * 2560 + row * 20 + q * 4) << 2),
                 Bgl + (size_t)(bn + row) * K + k0 + q * 8, 16);
        }
        cp_commit();
    };

    issue(0, 0);
    int p = 0;
    for (int k0 = 0; k0 < K; k0 += 32) {
        const bool more = (k0 + 32 < K);
        if (more) issue(p ^ 1, k0 + 32);
        if (more) cp_wait<1>(); else cp_wait<0>();
        __syncthreads();
        {
            const uint32_t baseAh = smb + (((p * 2 + 0) * 2560 + aoff) << 2);
            const uint32_t baseAl = smb + (((p * 2 + 1) * 2560 + aoff) << 2);
            const uint32_t baseBh = smb + ((10240 + (p * 2 + 0) * 2560 + boff) << 2);
            const uint32_t baseBl = smb + ((10240 + (p * 2 + 1) * 2560 + boff) << 2);
#pragma unroll
            for (int ks = 0; ks < 2; ks++) {
                uint32_t ah[4][4], al[4][4];
#pragma unroll
                for (int mt = 0; mt < 4; mt++) {
                    ldsm_x4(ah[mt][0], ah[mt][1], ah[mt][2], ah[mt][3],
                            baseAh + ((mt * 320 + ks * 8) << 2));
                    ldsm_x4(al[mt][0], al[mt][1], al[mt][2], al[mt][3],
                            baseAl + ((mt * 320 + ks * 8) << 2));
                }
#pragma unroll
                for (int j = 0; j < 4; j++) {
                    uint32_t bh0[2], bh1[2], bl0[2], bl1[2];
                    ldsm_x4(bh0[0], bh0[1], bh1[0], bh1[1],
                            baseBh + ((j * 320 + ks * 8) << 2));
                    ldsm_x4(bl0[0], bl0[1], bl1[0], bl1[1],
                            baseBl + ((j * 320 + ks * 8) << 2));
#pragma unroll
                    for (int mt = 0; mt < 4; mt++) {
                        mma_bf16(acc[mt][2 * j + 0], ah[mt], bh0);
                        mma_bf16(acc[mt][2 * j + 0], al[mt], bh0);
                        mma_bf16(acc[mt][2 * j + 0], ah[mt], bl0);
                        mma_bf16(acc[mt][2 * j + 1], ah[mt], bh1);
                        mma_bf16(acc[mt][2 * j + 1], al[mt], bh1);
                        mma_bf16(acc[mt][2 * j + 1], ah[mt], bl1);
                    }
                }
            }
        }
        __syncthreads();
        p ^= 1;
    }
#pragma unroll
    for (int mt = 0; mt < 4; mt++) {
        int r0 = bm + wm * 64 + mt * 16 + lg;
#pragma unroll
        for (int nt = 0; nt < 8; nt++) {
            int c0 = bn + wn * 64 + nt * 8 + lt * 2;
#pragma unroll
            for (int j = 0; j < 4; j++) {
                int row = r0 + (j >> 1) * 8;
                int col = c0 + (j & 1);
                if (row >= M) continue;
                float v = acc[mt][nt][j] + (bias ? bias[col] : 0.f);
                if (EP == EP_GATE) v = gateA[(size_t)row * K + col] * sigf(v);
                else if (EP == EP_RELU) v = fmaxf(v, 0.f);
                size_t idx = (size_t)row * N + col;
                if (WRITEC) C[idx] = v;
                if (SPLITOUT) {
                    bf16 h, l; bf_split(v, h, l);
                    Ch[idx] = h; Cl[idx] = l;
                }
            }
        }
    }
}

// ---------------- gemm8: BM=128 BN=128, 8 warps 64x32, cp.async + ldmatrix --
// 256 threads, launch_bounds(256,2) -> <=128 regs, 2 blocks/SM = 16 warps/SM.
template <int EP, bool SPLITOUT, bool WRITEC>
__global__ __launch_bounds__(256, 2) void gemm8(
    const bf16* __restrict__ Agh, const bf16* __restrict__ Agl,
    const bf16* __restrict__ Bgh, const bf16* __restrict__ Bgl,
    const float* __restrict__ bias, const float* __restrict__ gateA,
    float* __restrict__ C, bf16* __restrict__ Ch, bf16* __restrict__ Cl,
    int M, int K, int N) {
    extern __shared__ uint32_t smu[];
    const int bm = blockIdx.y * 128, bn = blockIdx.x * 128;
    const int tid = threadIdx.x, lane = tid & 31, wid = tid >> 5;
    const int wm = wid >> 2, wn = wid & 3;   // 2 x 4 warps; tile 64 x 32
    const int lg = lane >> 2, lt = lane & 3;
    const uint32_t smb = (uint32_t)__cvta_generic_to_shared(smu);

    const int lane7 = lane & 7;
    // A: same per-matrix grouping as gemm6 (proven)
    const int aoff = (wm * 64 + lane7 + ((lane >> 3) & 1) * 8) * 20 + ((lane >> 4) & 1) * 4;
    // B: 4 n8-blocks per ldsm_x4 at one k-half
    const int boff = (wn * 32 + lane7 + ((lane >> 3) & 3) * 8) * 20;

    float acc[4][4][4];
#pragma unroll
    for (int mt = 0; mt < 4; mt++)
#pragma unroll
        for (int nt = 0; nt < 4; nt++)
#pragma unroll
            for (int j = 0; j < 4; j++) acc[mt][nt][j] = 0.f;

    auto issue = [&](int p, int k0) {
#pragma unroll
        for (int i = 0; i < 2; i++) {
            int idx = tid + i * 256;
            int row = idx >> 2, q = idx & 3;
            int grow = bm + row;
            int sz = (grow < M) ? 16 : 0;
            int cg = (grow < M) ? grow : (M - 1);
            cp16(smb + (((p * 2 + 0) * 2560 + row * 20 + q * 4) << 2),
                 Agh + (size_t)cg * K + k0 + q * 8, sz);
            cp16(smb + (((p * 2 + 1) * 2560 + row * 20 + q * 4) << 2),
                 Agl + (size_t)cg * K + k0 + q * 8, sz);
            cp16(smb + ((10240 + (p * 2 + 0) * 2560 + row * 20 + q * 4) << 2),
                 Bgh + (size_t)(bn + row) * K + k0 + q * 8, 16);
            cp16(smb + ((10240 + (p * 2 + 1) * 2560 + row * 20 + q * 4) << 2),
                 Bgl + (size_t)(bn + row) * K + k0 + q * 8, 16);
        }
        cp_commit();
    };

    issue(0, 0);
    int p = 0;
    for (int k0 = 0; k0 < K; k0 += 32) {
        const bool more = (k0 + 32 < K);
        if (more) issue(p ^ 1, k0 + 32);
        if (more) cp_wait<1>(); else cp_wait<0>();
        __syncthreads();
        {
            const uint32_t baseAh = smb + (((p * 2 + 0) * 2560 + aoff) << 2);
            const uint32_t baseAl = smb + (((p * 2 + 1) * 2560 + aoff) << 2);
            const uint32_t baseBh = smb + ((10240 + (p * 2 + 0) * 2560 + boff) << 2);
            const uint32_t baseBl = smb + ((10240 + (p * 2 + 1) * 2560 + boff) << 2);
#pragma unroll
            for (int ks = 0; ks < 2; ks++) {
                uint32_t ah[4][4], al[4][4];
#pragma unroll
                for (int mt = 0; mt < 4; mt++) {
                    ldsm_x4(ah[mt][0], ah[mt][1], ah[mt][2], ah[mt][3],
                            baseAh + ((mt * 320 + ks * 8) << 2));
                    ldsm_x4(al[mt][0], al[mt][1], al[mt][2], al[mt][3],
                            baseAl + ((mt * 320 + ks * 8) << 2));
                }
                uint32_t bh0[4], bh8[4], bl0[4], bl8[4];
                ldsm_x4(bh0[0], bh0[1], bh0[2], bh0[3], baseBh + ((ks * 8 + 0) << 2));
                ldsm_x4(bh8[0], bh8[1], bh8[2], bh8[3], baseBh + ((ks * 8 + 4) << 2));
                ldsm_x4(bl0[0], bl0[1], bl0[2], bl0[3], baseBl + ((ks * 8 + 0) << 2));
                ldsm_x4(bl8[0], bl8[1], bl8[2], bl8[3], baseBl + ((ks * 8 + 4) << 2));
#pragma unroll
                for (int nt = 0; nt < 4; nt++) {
                    uint32_t bh[2] = { bh0[nt], bh8[nt] };
                    uint32_t bl[2] = { bl0[nt], bl8[nt] };
#pragma unroll
                    for (int mt = 0; mt < 4; mt++) {
                        mma_bf16(acc[mt][nt], ah[mt], bh);
                        mma_bf16(acc[mt][nt], al[mt], bh);
                        mma_bf16(acc[mt][nt], ah[mt], bl);
                    }
                }
            }
        }
        __syncthreads();
        p ^= 1;
    }
    // epilogue
#pragma unroll
    for (int mt = 0; mt < 4; mt++) {
        int r0 = bm + wm * 64 + mt * 16 + lg;
#pragma unroll
        for (int nt = 0; nt < 4; nt++) {
            int c0 = bn + wn * 32 + nt * 8 + lt * 2;
#pragma unroll
            for (int j = 0; j < 4; j++) {
                int row = r0 + (j >> 1) * 8;
                int col = c0 + (j & 1);
                if (row >= M) continue;
                float v = acc[mt][nt][j] + (bias ? bias[col] : 0.f);
                if (EP == EP_GATE) v = gateA[(size_t)row * K + col] * sigf(v);
                else if (EP == EP_RELU) v = fmaxf(v, 0.f);
                size_t idx = (size_t)row * N + col;
                if (WRITEC) C[idx] = v;
                if (SPLITOUT) {
                    bf16 h, l; bf_split(v, h, l);
                    Ch[idx] = h; Cl[idx] = l;
                }
            }
        }
    }
}

// ---------------- CSR build ----------------
__global__ void zero_kernel() {
    int i = blockIdx.x * blockDim.x + threadIdx.x;
    if (i < NN) { g_deg[i] = 0; g_cursor[i] = 0; g_easum[i] = 0.f; }
    if (i == 0) g_total = 0;
}
__global__ void deg_kernel(const int* __restrict__ dst, const float* __restrict__ ea) {
    int e = blockIdx.x * blockDim.x + threadIdx.x;
    if (e < NE) {
        int d = dst[e];
        atomicAdd(&g_deg[d], 1);
        atomicAdd(&g_easum[d], ea[e]);
    }
}
__global__ void loop_kernel() {
    int n = blockIdx.x * blockDim.x + threadIdx.x;
    if (n < NN) g_loop[n] = g_easum[n] / fmaxf((float)g_deg[n], 1.f);
}
__global__ void alloc_kernel() {
    __shared__ int s[1024];
    __shared__ int base;
    int tid = threadIdx.x;
    int i = blockIdx.x * 1024 + tid;
    int v = (i < NN) ? g_deg[i] : 0;
    s[tid] = v;
    __syncthreads();
    for (int off = 1; off < 1024; off <<= 1) {
        int t = (tid >= off) ? s[tid - off] : 0;
        __syncthreads();
        s[tid] += t;
        __syncthreads();
    }
    int incl = s[tid];
    if (tid == 1023) base = atomicAdd(&g_total, s[1023]);
    __syncthreads();
    if (i < NN) g_rowstart[i] = base + incl - v;
}
__global__ void csr_kernel(const int* __restrict__ dst) {
    int e = blockIdx.x * blockDim.x + threadIdx.x;
    if (e < NE) {
        int d = dst[e];
        int pos = atomicAdd(&g_cursor[d], 1);
        g_csr[g_rowstart[d] + pos] = e;
    }
}

// ---------------- attention coefficients ----------------
template <int H>
__global__ void attn_kernel(const float* __restrict__ hbuf, int stride,
                            const float* __restrict__ a_s, const float* __restrict__ a_d) {
    int w = (blockIdx.x * blockDim.x + threadIdx.x) >> 5;
    int lane = threadIdx.x & 31;
    if (w >= NN * H) return;
    int n = w / H, hh = w % H;
    const float* hr = hbuf + (size_t)n * stride + hh * 64;
    float as0 = a_s[hh * 64 + lane], as1 = a_s[hh * 64 + lane + 32];
    float ad0 = a_d[hh * 64 + lane], ad1 = a_d[hh * 64 + lane + 32];
    float h0 = hr[lane], h1 = hr[lane + 32];
    float vs = h0 * as0 + h1 * as1;
    float vd = h0 * ad0 + h1 * ad1;
#pragma unroll
    for (int off = 16; off > 0; off >>= 1) {
        vs += __shfl_down_sync(0xffffffffu, vs, off);
        vd += __shfl_down_sync(0xffffffffu, vd, off);
    }
    if (lane == 0) { g_asrc[w] = vs; g_adst[w] = vd; }
}

__global__ void ch_kernel(const float* __restrict__ We, const float* __restrict__ ae, int H, int C) {
    int h = threadIdx.x;
    if (h < H) {
        float s = 0.f;
        for (int c = 0; c < C; c++) s += We[h * C + c] * ae[h * C + c];
        g_ch[h] = s;
    }
}

// ---------------- per-node softmax aggregation (single pass, no max) -------
template <int H, int C, bool SPLIT, bool WRITEO>
__global__ void agg3(const float* __restrict__ hbuf, int hstride,
                     const int* __restrict__ src, const float* __restrict__ ea,
                     const float* __restrict__ bias,
                     const float* __restrict__ resid, int rstride,
                     float* __restrict__ out, bf16* __restrict__ outh,
                     bf16* __restrict__ outl) {
    constexpr int OUT = H * C;
    constexpr int CH = 64;
    __shared__ float s_alpha[CH * H];
    __shared__ int s_sid[CH];
    __shared__ float s_red[2 * H];

    const int n = blockIdx.x;
    const int tid = threadIdx.x;
    const int deg = g_deg[n];
    const int rs = g_rowstart[n];
    const int T = deg + 1;
    const float loopv = g_loop[n];

    float adst[H], chh[H], zloc[H];
#pragma unroll
    for (int h = 0; h < H; h++) zloc[h] = 0.f;
    if (tid < CH) {
#pragma unroll
        for (int h = 0; h < H; h++) { adst[h] = g_adst[n * H + h]; chh[h] = g_ch[h]; }
    }

    const int hh = tid / C;
    float acc = 0.f;
    for (int base = 0; base < T; base += CH) {
        int i = base + tid;
        if (tid < CH && i < T) {
            int sN; float eav;
            if (i < deg) { int e = g_csr[rs + i]; sN = src[e]; eav = ea[e]; }
            else { sN = n; eav = loopv; }
#pragma unroll
            for (int h = 0; h < H; h++) {
                float v = g_asrc[sN * H + h] + adst[h] + chh[h] * eav;
                v = (v >= 0.f) ? v : 0.2f * v;
                float ex = __expf(v);
                s_alpha[tid * H + h] = ex;
                zloc[h] += ex;
            }
            s_sid[tid] = sN;
        }
        __syncthreads();
        int lim = min(CH, T - base);
        for (int j = 0; j < lim; j++)
            acc += s_alpha[j * H + hh] * hbuf[(size_t)s_sid[j] * hstride + tid];
        __syncthreads();
    }
    if (tid < CH) {
#pragma unroll
        for (int off = 16; off > 0; off >>= 1)
#pragma unroll
            for (int h = 0; h < H; h++)
                zloc[h] += __shfl_xor_sync(0xffffffffu, zloc[h], off);
        if ((tid & 31) == 0) {
#pragma unroll
            for (int h = 0; h < H; h++) s_red[(tid >> 5) * H + h] = zloc[h];
        }
    }
    __syncthreads();
    float z = s_red[hh] + s_red[H + hh];
    float v = acc / z + bias[tid];
    v = (v >= 0.f) ? v : 0.01f * v;
    v += resid[(size_t)n * rstride + tid];
    size_t idx = (size_t)n * OUT + tid;
    if (WRITEO) out[idx] = v;
    if (SPLIT) {
        bf16 h, l; bf_split(v, h, l);
        outh[idx] = h; outl[idx] = l;
    }
}

// ---------------- driver ----------------
extern "C" void kernel_launch(void* const* d_in, const int* in_sizes, int n_in,
                              void* d_out, int out_size) {
    const float* x     = (const float*)d_in[0];
    const int*   eidx  = (const int*)d_in[1];
    const float* ea    = (const float*)d_in[2];
    const float* fa_w  = (const float*)d_in[3];
    const float* fa_b  = (const float*)d_in[4];
    const float* W1    = (const float*)d_in[5];
    const float* We1   = (const float*)d_in[6];
    const float* as1   = (const float*)d_in[7];
    const float* ad1   = (const float*)d_in[8];
    const float* ae1   = (const float*)d_in[9];
    const float* b1    = (const float*)d_in[10];
    const float* W2    = (const float*)d_in[11];
    const float* We2   = (const float*)d_in[12];
    const float* as2   = (const float*)d_in[13];
    const float* ad2   = (const float*)d_in[14];
    const float* ae2   = (const float*)d_in[15];
    const float* b2    = (const float*)d_in[16];
    const float* W3    = (const float*)d_in[17];
    const float* We3   = (const float*)d_in[18];
    const float* as3   = (const float*)d_in[19];
    const float* ad3   = (const float*)d_in[20];
    const float* ae3   = (const float*)d_in[21];
    const float* b3    = (const float*)d_in[22];
    const float* r1_w  = (const float*)d_in[23];
    const float* r1_b  = (const float*)d_in[24];
    const float* r2_w  = (const float*)d_in[25];
    const float* r2_b  = (const float*)d_in[26];
    const float* ffn_w1 = (const float*)d_in[27];
    const float* ffn_b1 = (const float*)d_in[28];
    const float* ffn_w2 = (const float*)d_in[29];
    const float* ffn_b2 = (const float*)d_in[30];
    float* out = (float*)d_out;

    const int* src = eidx;
    const int* dst = eidx + NE;

    bf16 *xh, *xl, *gxh, *gxl, *z1h, *z1l, *z2h, *z2l, *t64h, *t64l;
    bf16 *wfah, *wfal, *wb1h, *wb1l, *wb2h, *wb2l, *w3h, *w3l, *wf1h, *wf1l, *wf2h, *wf2l;
    float *hr, *zself, *h3, *bb1, *bb2;
    cudaGetSymbolAddress((void**)&xh, g_xh);   cudaGetSymbolAddress((void**)&xl, g_xl);
    cudaGetSymbolAddress((void**)&gxh, g_gxh); cudaGetSymbolAddress((void**)&gxl, g_gxl);
    cudaGetSymbolAddress((void**)&hr, g_hr);
    cudaGetSymbolAddress((void**)&z1h, g_z1h); cudaGetSymbolAddress((void**)&z1l, g_z1l);
    cudaGetSymbolAddress((void**)&z2h, g_z2h); cudaGetSymbolAddress((void**)&z2l, g_z2l);
    cudaGetSymbolAddress((void**)&t64h, g_t64h); cudaGetSymbolAddress((void**)&t64l, g_t64l);
    cudaGetSymbolAddress((void**)&zself, g_zself);
    cudaGetSymbolAddress((void**)&h3, g_h3);
    cudaGetSymbolAddress((void**)&wfah, g_wfa_h); cudaGetSymbolAddress((void**)&wfal, g_wfa_l);
    cudaGetSymbolAddress((void**)&wb1h, g_wb1_h); cudaGetSymbolAddress((void**)&wb1l, g_wb1_l);
    cudaGetSymbolAddress((void**)&wb2h, g_wb2_h); cudaGetSymbolAddress((void**)&wb2l, g_wb2_l);
    cudaGetSymbolAddress((void**)&w3h, g_w3_h);   cudaGetSymbolAddress((void**)&w3l, g_w3_l);
    cudaGetSymbolAddress((void**)&wf1h, g_wf1_h); cudaGetSymbolAddress((void**)&wf1l, g_wf1_l);
    cudaGetSymbolAddress((void**)&wf2h, g_wf2_h); cudaGetSymbolAddress((void**)&wf2l, g_wf2_l);
    cudaGetSymbolAddress((void**)&bb1, g_bb1);
    cudaGetSymbolAddress((void**)&bb2, g_bb2);

    cudaFuncSetAttribute(gemm5<EP_RELU, true, false>,
                         cudaFuncAttributeMaxDynamicSharedMemorySize, SMEM_DB);
    cudaFuncSetAttribute(gemm5<EP_NONE, false, true>,
                         cudaFuncAttributeMaxDynamicSharedMemorySize, SMEM_DB);
    cudaFuncSetAttribute(gemm6<EP_GATE, true, false>,
                         cudaFuncAttributeMaxDynamicSharedMemorySize, SMEM2);
    cudaFuncSetAttribute(gemm8<EP_NONE, false, true>,
                         cudaFuncAttributeMaxDynamicSharedMemorySize, SMEM2);

    const int TB = 256;
    const int nbN = (NN + TB - 1) / TB;
    const int nbE = (NE + TB - 1) / TB;
    const int gy = (NN + 127) / 128;

    // launch 1: weight prep for gate + layer1
    packall_kernel<<<(82944 + 255) / 256, 256>>>(fa_w, r1_w, W1, r1_b, r2_b);
    // launch 2: split x
    split_bf_kernel<<<(NN * 128 + 255) / 256, 256>>>(x, xh, xl, NN * 128);
    // launch 3: gate gemm (N=128, gemm6)
    gemm6<EP_GATE, true, false><<<dim3(1, gy), 128, SMEM2>>>(
        xh, xl, wfah, wfal, fa_b, x, nullptr, gxh, gxl, NN, 128, 128);
    // launch 4: layer-1 GEMM (N=512, gemm8)  <-- profiled launch
    gemm8<EP_NONE, false, true><<<dim3(4, gy), 256, SMEM2>>>(
        gxh, gxl, wb1h, wb1l, bb1, nullptr, hr, nullptr, nullptr, NN, 128, 512);

    // CSR build
    zero_kernel<<<nbN, TB>>>();
    deg_kernel<<<nbE, TB>>>(dst, ea);
    loop_kernel<<<nbN, TB>>>();
    alloc_kernel<<<(NN + 1023) / 1024, 1024>>>();
    csr_kernel<<<nbE, TB>>>(dst);

    // remaining weight packs
    packfuseT_kernel<<<(512 * 256 + 255) / 256, 256>>>(r2_w, W2, wb2h, wb2l, 256, 256);
    packT_kernel<<<(64 * 256 + 255) / 256, 256>>>(W3, w3h, w3l, 256, 64);
    packT_kernel<<<(64 * 128 + 255) / 256, 256>>>(ffn_w1, wf1h, wf1l, 128, 64);
    packT_kernel<<<(64 * 64 + 255) / 256, 256>>>(ffn_w2, wf2h, wf2l, 64, 64);

    // ffn path (N=64 -> gemm5)
    gemm5<EP_RELU, true, false><<<dim3(1, gy), 256, SMEM_DB>>>(
        gxh, gxl, wf1h, wf1l, ffn_b1, nullptr, nullptr, t64h, t64l, NN, 128, 64);
    gemm5<EP_NONE, false, true><<<dim3(1, gy), 256, SMEM_DB>>>(
        t64h, t64l, wf2h, wf2l, ffn_b2, nullptr, zself, nullptr, nullptr, NN, 64, 64);

    // layer 1 attention + aggregation
    attn_kernel<4><<<(NN * 4 * 32 + TB - 1) / TB, TB>>>(hr + 256, 512, as1, ad1);
    ch_kernel<<<1, 4>>>(We1, ae1, 4, 64);
    agg3<4, 64, true, false><<<NN, 256>>>(hr + 256, 512, src, ea, b1, hr, 512,
                                          nullptr, z1h, z1l);

    // layer 2 (gemm8)
    gemm8<EP_NONE, false, true><<<dim3(4, gy), 256, SMEM2>>>(
        z1h, z1l, wb2h, wb2l, bb2, nullptr, hr, nullptr, nullptr, NN, 256, 512);
    attn_kernel<4><<<(NN * 4 * 32 + TB - 1) / TB, TB>>>(hr + 256, 512, as2, ad2);
    ch_kernel<<<1, 4>>>(We2, ae2, 4, 64);
    agg3<4, 64, true, false><<<NN, 256>>>(hr + 256, 512, src, ea, b2, hr, 512,
                                          nullptr, z2h, z2l);

    // layer 3 (N=64 -> gemm5)
    gemm5<EP_NONE, false, true><<<dim3(1, gy), 256, SMEM_DB>>>(
        z2h, z2l, w3h, w3l, nullptr, nullptr, h3, nullptr, nullptr, NN, 256, 64);
    attn_kernel<1><<<(NN * 32 + TB - 1) / TB, TB>>>(h3, 64, as3, ad3);
    ch_kernel<<<1, 1>>>(We3, ae3, 1, 64);
    agg3<1, 64, false, true><<<NN, 64>>>(h3, 64, src, ea, b3, zself, 64,
                                         out, nullptr, nullptr);
}

// round 14
// speedup vs baseline: 1.0268x; 1.0268x over previous
#include <cuda_runtime.h>
#include <cuda_bf16.h>
#include <math.h>
#include <stdint.h>

#define NN 50000
#define NE 800000

typedef __nv_bfloat16 bf16;

// ---------------- scratch (device globals) ----------------
__device__ __align__(16) bf16 g_xh[NN * 128], g_xl[NN * 128];
__device__ __align__(16) bf16 g_gxh[NN * 128], g_gxl[NN * 128];
__device__ float g_hr[NN * 512];                          // [res | h] fused layer out
__device__ __align__(16) bf16 g_z1h[NN * 256], g_z1l[NN * 256];
__device__ __align__(16) bf16 g_z2h[NN * 256], g_z2l[NN * 256];
__device__ __align__(16) bf16 g_t64h[NN * 64], g_t64l[NN * 64];
__device__ float g_zself[NN * 64];
__device__ float g_h3[NN * 64];
__device__ float g_asrc[NN * 4];
__device__ float g_adst[NN * 4];
__device__ float g_loop[NN];
__device__ float g_easum[NN];
__device__ int   g_deg[NN];
__device__ int   g_rowstart[NN];
__device__ int   g_cursor[NN];
__device__ int   g_csr[NE];
__device__ float g_chv[12];     // [0..3] layer1, [4..7] layer2, [8] layer3
__device__ int   g_total;
// transposed [n][k] k-major bf16 weight splits
__device__ __align__(16) bf16 g_wfa_h[128 * 128], g_wfa_l[128 * 128];
__device__ __align__(16) bf16 g_wb1_h[512 * 128], g_wb1_l[512 * 128];
__device__ __align__(16) bf16 g_wb2_h[512 * 256], g_wb2_l[512 * 256];
__device__ __align__(16) bf16 g_w3_h[64 * 256],  g_w3_l[64 * 256];
__device__ __align__(16) bf16 g_wf1_h[64 * 128], g_wf1_l[64 * 128];
__device__ __align__(16) bf16 g_wf2_h[64 * 64],  g_wf2_l[64 * 64];
__device__ float g_bb1[512], g_bb2[512];

__device__ __forceinline__ float sigf(float x) { return 1.f / (1.f + __expf(-x)); }

__device__ __forceinline__ void bf_split(float x, bf16& h, bf16& l) {
    h = __float2bfloat16(x);
    l = __float2bfloat16(x - __bfloat162float(h));
}

__device__ __forceinline__ void mma_bf16(float* c, const uint32_t* a, const uint32_t* b) {
    asm volatile(
        "mma.sync.aligned.m16n8k16.row.col.f32.bf16.bf16.f32 "
        "{%0,%1,%2,%3}, {%4,%5,%6,%7}, {%8,%9}, {%0,%1,%2,%3};\n"
        : "+f"(c[0]), "+f"(c[1]), "+f"(c[2]), "+f"(c[3])
        : "r"(a[0]), "r"(a[1]), "r"(a[2]), "r"(a[3]), "r"(b[0]), "r"(b[1]));
}

__device__ __forceinline__ void ldsm_x4(uint32_t& r0, uint32_t& r1, uint32_t& r2,
                                        uint32_t& r3, uint32_t addr) {
    asm volatile("ldmatrix.sync.aligned.m8n8.x4.shared.b16 {%0,%1,%2,%3}, [%4];"
                 : "=r"(r0), "=r"(r1), "=r"(r2), "=r"(r3) : "r"(addr));
}

__device__ __forceinline__ void cp16(uint32_t dst, const void* src, int sz) {
    asm volatile("cp.async.cg.shared.global [%0], [%1], 16, %2;\n"
                 :: "r"(dst), "l"(src), "r"(sz));
}
__device__ __forceinline__ void cp_commit() {
    asm volatile("cp.async.commit_group;\n");
}
template <int N>
__device__ __forceinline__ void cp_wait() {
    asm volatile("cp.async.wait_group %0;\n" :: "n"(N));
}

// ---------------- pack / split kernels ----------------
__global__ void split_bf_kernel(const float* __restrict__ s, bf16* __restrict__ dh,
                                bf16* __restrict__ dl, int n) {
    int i = blockIdx.x * blockDim.x + threadIdx.x;
    if (i < n) { bf16 h, l; bf_split(s[i], h, l); dh[i] = h; dl[i] = l; }
}
__global__ void packall_kernel(const float* __restrict__ fa_w,
                               const float* __restrict__ r1_w, const float* __restrict__ W1,
                               const float* __restrict__ r1_b, const float* __restrict__ r2_b) {
    int i = blockIdx.x * blockDim.x + threadIdx.x;
    if (i < 16384) {
        int n = i >> 7, k = i & 127;
        bf16 h, l; bf_split(fa_w[k * 128 + n], h, l);
        g_wfa_h[i] = h; g_wfa_l[i] = l;
    } else if (i < 16384 + 65536) {
        int j = i - 16384;
        int n = j >> 7, k = j & 127;
        float v = (n < 256) ? r1_w[k * 256 + n] : W1[k * 256 + n - 256];
        bf16 h, l; bf_split(v, h, l);
        g_wb1_h[j] = h; g_wb1_l[j] = l;
    } else if (i < 16384 + 65536 + 512) {
        int j = i - 81920;
        g_bb1[j] = (j < 256) ? r1_b[j] : 0.f;
    } else if (i < 16384 + 65536 + 1024) {
        int j = i - 82432;
        g_bb2[j] = (j < 256) ? r2_b[j] : 0.f;
    }
}
__global__ void packT_kernel(const float* __restrict__ W, bf16* __restrict__ th,
                             bf16* __restrict__ tl, int K_, int N_) {
    int i = blockIdx.x * blockDim.x + threadIdx.x;
    if (i < K_ * N_) {
        int n = i / K_, k = i % K_;
        bf16 h, l; bf_split(W[k * N_ + n], h, l);
        th[i] = h; tl[i] = l;
    }
}
__global__ void packfuseT_kernel(const float* __restrict__ A_, const float* __restrict__ B_,
                                 bf16* __restrict__ th, bf16* __restrict__ tl,
                                 int K_, int half) {
    int i = blockIdx.x * blockDim.x + threadIdx.x;
    if (i < 2 * half * K_) {
        int n = i / K_, k = i % K_;
        float v = (n < half) ? A_[k * half + n] : B_[k * half + n - half];
        bf16 h, l; bf_split(v, h, l);
        th[i] = h; tl[i] = l;
    }
}
// all per-head edge-attention constants in one launch
__global__ void ch123_kernel(const float* __restrict__ We1, const float* __restrict__ ae1,
                             const float* __restrict__ We2, const float* __restrict__ ae2,
                             const float* __restrict__ We3, const float* __restrict__ ae3) {
    int t = threadIdx.x;
    if (t < 4) {
        float s = 0.f;
        for (int c = 0; c < 64; c++) s += We1[t * 64 + c] * ae1[t * 64 + c];
        g_chv[t] = s;
    } else if (t < 8) {
        int h = t - 4;
        float s = 0.f;
        for (int c = 0; c < 64; c++) s += We2[h * 64 + c] * ae2[h * 64 + c];
        g_chv[4 + h] = s;
    } else if (t == 8) {
        float s = 0.f;
        for (int c = 0; c < 64; c++) s += We3[c] * ae3[c];
        g_chv[8] = s;
    }
}

#define EP_NONE 0
#define EP_GATE 1
#define EP_RELU 2

// ---------------- gemm5: bf16x3 m16n8k16, BM=128 BN=64 BK=32 (N=64 cases) --
#define SMEM_DB (15360 * 4)

template <int EP, bool SPLITOUT, bool WRITEC>
__global__ __launch_bounds__(256) void gemm5(
    const bf16* __restrict__ Agh, const bf16* __restrict__ Agl,
    const bf16* __restrict__ Bgh, const bf16* __restrict__ Bgl,
    const float* __restrict__ bias, const float* __restrict__ gateA,
    float* __restrict__ C, bf16* __restrict__ Ch, bf16* __restrict__ Cl,
    int M, int K, int N) {
    extern __shared__ uint32_t smu[];
    const int bm = blockIdx.y * 128, bn = blockIdx.x * 64;
    const int tid = threadIdx.x, lane = tid & 31, wid = tid >> 5;
    const int wm = wid >> 1, wn = wid & 1;
    const int lg = lane >> 2, lt = lane & 3;
    const int arow = tid >> 2, q = tid & 3;

    float acc[2][4][4];
#pragma unroll
    for (int mt = 0; mt < 2; mt++)
#pragma unroll
        for (int nt = 0; nt < 4; nt++)
#pragma unroll
            for (int j = 0; j < 4; j++) acc[mt][nt][j] = 0.f;

    uint4 rA[2][2], rB[2];
    const uint4 z16 = make_uint4(0u, 0u, 0u, 0u);

#pragma unroll
    for (int t = 0; t < 2; t++) {
        int grow = bm + arow + t * 64;
        if (grow < M) {
            rA[t][0] = ((const uint4*)(Agh + (size_t)grow * K))[q];
            rA[t][1] = ((const uint4*)(Agl + (size_t)grow * K))[q];
        } else { rA[t][0] = z16; rA[t][1] = z16; }
    }
    rB[0] = ((const uint4*)(Bgh + (size_t)(bn + arow) * K))[q];
    rB[1] = ((const uint4*)(Bgl + (size_t)(bn + arow) * K))[q];

    int p = 0;
    {
#pragma unroll
        for (int t = 0; t < 2; t++) {
            int row = arow + t * 64;
#pragma unroll
            for (int s = 0; s < 2; s++) {
                uint32_t* d = smu + s * 2560 + row * 20 + q * 4;
                uint4 v = rA[t][s];
                d[0] = v.x; d[1] = v.y; d[2] = v.z; d[3] = v.w;
            }
        }
#pragma unroll
        for (int s = 0; s < 2; s++) {
            uint32_t* d = smu + 10240 + s * 1280 + arow * 20 + q * 4;
            uint4 v = rB[s];
            d[0] = v.x; d[1] = v.y; d[2] = v.z; d[3] = v.w;
        }
    }
    __syncthreads();

    for (int k0 = 0; k0 < K; k0 += 32) {
        const bool more = (k0 + 32 < K);
        if (more) {
            int kn = k0 + 32;
#pragma unroll
            for (int t = 0; t < 2; t++) {
                int grow = bm + arow + t * 64;
                if (grow < M) {
                    rA[t][0] = ((const uint4*)(Agh + (size_t)grow * K + kn))[q];
                    rA[t][1] = ((const uint4*)(Agl + (size_t)grow * K + kn))[q];
                } else { rA[t][0] = z16; rA[t][1] = z16; }
            }
            rB[0] = ((const uint4*)(Bgh + (size_t)(bn + arow) * K + kn))[q];
            rB[1] = ((const uint4*)(Bgl + (size_t)(bn + arow) * K + kn))[q];
        }
        {
            const uint32_t* Ah = smu + (p * 2 + 0) * 2560;
            const uint32_t* Al = smu + (p * 2 + 1) * 2560;
            const uint32_t* Bh = smu + 10240 + (p * 2 + 0) * 1280;
            const uint32_t* Bl = smu + 10240 + (p * 2 + 1) * 1280;
#pragma unroll
            for (int ks = 0; ks < 2; ks++) {
                const int kp = ks * 8 + lt;
                uint32_t ah[2][4], al[2][4];
#pragma unroll
                for (int mt = 0; mt < 2; mt++) {
                    int r = wm * 32 + mt * 16 + lg;
                    ah[mt][0] = Ah[r * 20 + kp];
                    ah[mt][1] = Ah[(r + 8) * 20 + kp];
                    ah[mt][2] = Ah[r * 20 + kp + 4];
                    ah[mt][3] = Ah[(r + 8) * 20 + kp + 4];
                    al[mt][0] = Al[r * 20 + kp];
                    al[mt][1] = Al[(r + 8) * 20 + kp];
                    al[mt][2] = Al[r * 20 + kp + 4];
                    al[mt][3] = Al[(r + 8) * 20 + kp + 4];
                }
#pragma unroll
                for (int nt = 0; nt < 4; nt++) {
                    int c = wn * 32 + nt * 8 + lg;
                    uint32_t bh[2], bl2[2];
                    bh[0] = Bh[c * 20 + kp];
                    bh[1] = Bh[c * 20 + kp + 4];
                    bl2[0] = Bl[c * 20 + kp];
                    bl2[1] = Bl[c * 20 + kp + 4];
#pragma unroll
                    for (int mt = 0; mt < 2; mt++) {
                        mma_bf16(acc[mt][nt], ah[mt], bh);
                        mma_bf16(acc[mt][nt], al[mt], bh);
                        mma_bf16(acc[mt][nt], ah[mt], bl2);
                    }
                }
            }
        }
        if (more) {
            int pb = p ^ 1;
#pragma unroll
            for (int t = 0; t < 2; t++) {
                int row = arow + t * 64;
#pragma unroll
                for (int s = 0; s < 2; s++) {
                    uint32_t* d = smu + (pb * 2 + s) * 2560 + row * 20 + q * 4;
                    uint4 v = rA[t][s];
                    d[0] = v.x; d[1] = v.y; d[2] = v.z; d[3] = v.w;
                }
            }
#pragma unroll
            for (int s = 0; s < 2; s++) {
                uint32_t* d = smu + 10240 + (pb * 2 + s) * 1280 + arow * 20 + q * 4;
                uint4 v = rB[s];
                d[0] = v.x; d[1] = v.y; d[2] = v.z; d[3] = v.w;
            }
            __syncthreads();
            p = pb;
        }
    }
#pragma unroll
    for (int mt = 0; mt < 2; mt++) {
        int r0 = bm + wm * 32 + mt * 16 + lg;
#pragma unroll
        for (int nt = 0; nt < 4; nt++) {
            int c0 = bn + wn * 32 + nt * 8 + lt * 2;
#pragma unroll
            for (int j = 0; j < 4; j++) {
                int row = r0 + (j >> 1) * 8;
                int col = c0 + (j & 1);
                if (row >= M) continue;
                float v = acc[mt][nt][j] + (bias ? bias[col] : 0.f);
                if (EP == EP_GATE) v = gateA[(size_t)row * K + col] * sigf(v);
                else if (EP == EP_RELU) v = fmaxf(v, 0.f);
                size_t idx = (size_t)row * N + col;
                if (WRITEC) C[idx] = v;
                if (SPLITOUT) {
                    bf16 h, l; bf_split(v, h, l);
                    Ch[idx] = h; Cl[idx] = l;
                }
            }
        }
    }
}

// ---------------- gemm6: BM=128 BN=128, 4 warps 64x64, cp.async + ldmatrix --
#define SMEM2 (20480 * 4)

template <int EP, bool SPLITOUT, bool WRITEC>
__global__ __launch_bounds__(128) void gemm6(
    const bf16* __restrict__ Agh, const bf16* __restrict__ Agl,
    const bf16* __restrict__ Bgh, const bf16* __restrict__ Bgl,
    const float* __restrict__ bias, const float* __restrict__ gateA,
    float* __restrict__ C, bf16* __restrict__ Ch, bf16* __restrict__ Cl,
    int M, int K, int N) {
    extern __shared__ uint32_t smu[];
    const int bm = blockIdx.y * 128, bn = blockIdx.x * 128;
    const int tid = threadIdx.x, lane = tid & 31, wid = tid >> 5;
    const int wm = wid >> 1, wn = wid & 1;
    const int lg = lane >> 2, lt = lane & 3;
    const uint32_t smb = (uint32_t)__cvta_generic_to_shared(smu);

    const int lane7 = lane & 7;
    const int aoff = (wm * 64 + lane7 + ((lane >> 3) & 1) * 8) * 20 + ((lane >> 4) & 1) * 4;
    const int boff = (wn * 64 + lane7 + ((lane >> 4) & 1) * 8) * 20 + ((lane >> 3) & 1) * 4;

    float acc[4][8][4];
#pragma unroll
    for (int mt = 0; mt < 4; mt++)
#pragma unroll
        for (int nt = 0; nt < 8; nt++)
#pragma unroll
            for (int j = 0; j < 4; j++) acc[mt][nt][j] = 0.f;

    auto issue = [&](int p, int k0) {
#pragma unroll
        for (int i = 0; i < 4; i++) {
            int idx = tid + i * 128;
            int row = idx >> 2, q = idx & 3;
            int grow = bm + row;
            int sz = (grow < M) ? 16 : 0;
            int cg = (grow < M) ? grow : (M - 1);
            cp16(smb + (((p * 2 + 0) * 2560 + row * 20 + q * 4) << 2),
                 Agh + (size_t)cg * K + k0 + q * 8, sz);
            cp16(smb + (((p * 2 + 1) * 2560 + row * 20 + q * 4) << 2),
                 Agl + (size_t)cg * K + k0 + q * 8, sz);
            cp16(smb + ((10240 + (p * 2 + 0) * 2560 + row * 20 + q * 4) << 2),
                 Bgh + (size_t)(bn + row) * K + k0 + q * 8, 16);
            cp16(smb + ((10240 + (p * 2 + 1) * 2560 + row * 20 + q * 4) << 2),
                 Bgl + (size_t)(bn + row) * K + k0 + q * 8, 16);
        }
        cp_commit();
    };

    issue(0, 0);
    int p = 0;
    for (int k0 = 0; k0 < K; k0 += 32) {
        const bool more = (k0 + 32 < K);
        if (more) issue(p ^ 1, k0 + 32);
        if (more) cp_wait<1>(); else cp_wait<0>();
        __syncthreads();
        {
            const uint32_t baseAh = smb + (((p * 2 + 0) * 2560 + aoff) << 2);
            const uint32_t baseAl = smb + (((p * 2 + 1) * 2560 + aoff) << 2);
            const uint32_t baseBh = smb + ((10240 + (p * 2 + 0) * 2560 + boff) << 2);
            const uint32_t baseBl = smb + ((10240 + (p * 2 + 1) * 2560 + boff) << 2);
#pragma unroll
            for (int ks = 0; ks < 2; ks++) {
                uint32_t ah[4][4], al[4][4];
#pragma unroll
                for (int mt = 0; mt < 4; mt++) {
                    ldsm_x4(ah[mt][0], ah[mt][1], ah[mt][2], ah[mt][3],
                            baseAh + ((mt * 320 + ks * 8) << 2));
                    ldsm_x4(al[mt][0], al[mt][1], al[mt][2], al[mt][3],
                            baseAl + ((mt * 320 + ks * 8) << 2));
                }
#pragma unroll
                for (int j = 0; j < 4; j++) {
                    uint32_t bh0[2], bh1[2], bl0[2], bl1[2];
                    ldsm_x4(bh0[0], bh0[1], bh1[0], bh1[1],
                            baseBh + ((j * 320 + ks * 8) << 2));
                    ldsm_x4(bl0[0], bl0[1], bl1[0], bl1[1],
                            baseBl + ((j * 320 + ks * 8) << 2));
#pragma unroll
                    for (int mt = 0; mt < 4; mt++) {
                        mma_bf16(acc[mt][2 * j + 0], ah[mt], bh0);
                        mma_bf16(acc[mt][2 * j + 0], al[mt], bh0);
                        mma_bf16(acc[mt][2 * j + 0], ah[mt], bl0);
                        mma_bf16(acc[mt][2 * j + 1], ah[mt], bh1);
                        mma_bf16(acc[mt][2 * j + 1], al[mt], bh1);
                        mma_bf16(acc[mt][2 * j + 1], ah[mt], bl1);
                    }
                }
            }
        }
        __syncthreads();
        p ^= 1;
    }
#pragma unroll
    for (int mt = 0; mt < 4; mt++) {
        int r0 = bm + wm * 64 + mt * 16 + lg;
#pragma unroll
        for (int nt = 0; nt < 8; nt++) {
            int c0 = bn + wn * 64 + nt * 8 + lt * 2;
#pragma unroll
            for (int j = 0; j < 4; j++) {
                int row = r0 + (j >> 1) * 8;
                int col = c0 + (j & 1);
                if (row >= M) continue;
                float v = acc[mt][nt][j] + (bias ? bias[col] : 0.f);
                if (EP == EP_GATE) v = gateA[(size_t)row * K + col] * sigf(v);
                else if (EP == EP_RELU) v = fmaxf(v, 0.f);
                size_t idx = (size_t)row * N + col;
                if (WRITEC) C[idx] = v;
                if (SPLITOUT) {
                    bf16 h, l; bf_split(v, h, l);
                    Ch[idx] = h; Cl[idx] = l;
                }
            }
        }
    }
}

// ---------------- CSR build ----------------
__global__ void zero_kernel() {
    int i = blockIdx.x * blockDim.x + threadIdx.x;
    if (i < NN) { g_deg[i] = 0; g_cursor[i] = 0; g_easum[i] = 0.f; }
    if (i == 0) g_total = 0;
}
__global__ void deg_kernel(const int* __restrict__ dst, const float* __restrict__ ea) {
    int e = blockIdx.x * blockDim.x + threadIdx.x;
    if (e < NE) {
        int d = dst[e];
        atomicAdd(&g_deg[d], 1);
        atomicAdd(&g_easum[d], ea[e]);
    }
}
// rowstart allocation + self-loop attr, fused
__global__ void alloc_kernel() {
    __shared__ int s[1024];
    __shared__ int base;
    int tid = threadIdx.x;
    int i = blockIdx.x * 1024 + tid;
    int v = (i < NN) ? g_deg[i] : 0;
    s[tid] = v;
    __syncthreads();
    for (int off = 1; off < 1024; off <<= 1) {
        int t = (tid >= off) ? s[tid - off] : 0;
        __syncthreads();
        s[tid] += t;
        __syncthreads();
    }
    int incl = s[tid];
    if (tid == 1023) base = atomicAdd(&g_total, s[1023]);
    __syncthreads();
    if (i < NN) {
        g_rowstart[i] = base + incl - v;
        g_loop[i] = g_easum[i] / fmaxf((float)v, 1.f);
    }
}
__global__ void csr_kernel(const int* __restrict__ dst) {
    int e = blockIdx.x * blockDim.x + threadIdx.x;
    if (e < NE) {
        int d = dst[e];
        int pos = atomicAdd(&g_cursor[d], 1);
        g_csr[g_rowstart[d] + pos] = e;
    }
}

// ---------------- attention coefficients ----------------
template <int H>
__global__ void attn_kernel(const float* __restrict__ hbuf, int stride,
                            const float* __restrict__ a_s, const float* __restrict__ a_d) {
    int w = (blockIdx.x * blockDim.x + threadIdx.x) >> 5;
    int lane = threadIdx.x & 31;
    if (w >= NN * H) return;
    int n = w / H, hh = w % H;
    const float* hr = hbuf + (size_t)n * stride + hh * 64;
    float as0 = a_s[hh * 64 + lane], as1 = a_s[hh * 64 + lane + 32];
    float ad0 = a_d[hh * 64 + lane], ad1 = a_d[hh * 64 + lane + 32];
    float h0 = hr[lane], h1 = hr[lane + 32];
    float vs = h0 * as0 + h1 * as1;
    float vd = h0 * ad0 + h1 * ad1;
#pragma unroll
    for (int off = 16; off > 0; off >>= 1) {
        vs += __shfl_down_sync(0xffffffffu, vs, off);
        vd += __shfl_down_sync(0xffffffffu, vd, off);
    }
    if (lane == 0) { g_asrc[w] = vs; g_adst[w] = vd; }
}

// ---------------- per-node softmax aggregation (single pass, no max) -------
template <int H, int C, bool SPLIT, bool WRITEO>
__global__ void agg3(const float* __restrict__ hbuf, int hstride,
                     const int* __restrict__ src, const float* __restrict__ ea,
                     const float* __restrict__ bias, int choff,
                     const float* __restrict__ resid, int rstride,
                     float* __restrict__ out, bf16* __restrict__ outh,
                     bf16* __restrict__ outl) {
    constexpr int OUT = H * C;
    constexpr int CH = 64;
    __shared__ float s_alpha[CH * H];
    __shared__ int s_sid[CH];
    __shared__ float s_red[2 * H];

    const int n = blockIdx.x;
    const int tid = threadIdx.x;
    const int deg = g_deg[n];
    const int rs = g_rowstart[n];
    const int T = deg + 1;
    const float loopv = g_loop[n];

    float adst[H], chh[H], zloc[H];
#pragma unroll
    for (int h = 0; h < H; h++) zloc[h] = 0.f;
    if (tid < CH) {
#pragma unroll
        for (int h = 0; h < H; h++) { adst[h] = g_adst[n * H + h]; chh[h] = g_chv[choff + h]; }
    }

    const int hh = tid / C;
    float acc = 0.f;
    for (int base = 0; base < T; base += CH) {
        int i = base + tid;
        if (tid < CH && i < T) {
            int sN; float eav;
            if (i < deg) { int e = g_csr[rs + i]; sN = src[e]; eav = ea[e]; }
            else { sN = n; eav = loopv; }
#pragma unroll
            for (int h = 0; h < H; h++) {
                float v = g_asrc[sN * H + h] + adst[h] + chh[h] * eav;
                v = (v >= 0.f) ? v : 0.2f * v;
                float ex = __expf(v);
                s_alpha[tid * H + h] = ex;
                zloc[h] += ex;
            }
            s_sid[tid] = sN;
        }
        __syncthreads();
        int lim = min(CH, T - base);
        for (int j = 0; j < lim; j++)
            acc += s_alpha[j * H + hh] * hbuf[(size_t)s_sid[j] * hstride + tid];
        __syncthreads();
    }
    if (tid < CH) {
#pragma unroll
        for (int off = 16; off > 0; off >>= 1)
#pragma unroll
            for (int h = 0; h < H; h++)
                zloc[h] += __shfl_xor_sync(0xffffffffu, zloc[h], off);
        if ((tid & 31) == 0) {
#pragma unroll
            for (int h = 0; h < H; h++) s_red[(tid >> 5) * H + h] = zloc[h];
        }
    }
    __syncthreads();
    float z = s_red[hh] + s_red[H + hh];
    float v = acc / z + bias[tid];
    v = (v >= 0.f) ? v : 0.01f * v;
    v += resid[(size_t)n * rstride + tid];
    size_t idx = (size_t)n * OUT + tid;
    if (WRITEO) out[idx] = v;
    if (SPLIT) {
        bf16 h, l; bf_split(v, h, l);
        outh[idx] = h; outl[idx] = l;
    }
}

// ---------------- driver ----------------
extern "C" void kernel_launch(void* const* d_in, const int* in_sizes, int n_in,
                              void* d_out, int out_size) {
    const float* x     = (const float*)d_in[0];
    const int*   eidx  = (const int*)d_in[1];
    const float* ea    = (const float*)d_in[2];
    const float* fa_w  = (const float*)d_in[3];
    const float* fa_b  = (const float*)d_in[4];
    const float* W1    = (const float*)d_in[5];
    const float* We1   = (const float*)d_in[6];
    const float* as1   = (const float*)d_in[7];
    const float* ad1   = (const float*)d_in[8];
    const float* ae1   = (const float*)d_in[9];
    const float* b1    = (const float*)d_in[10];
    const float* W2    = (const float*)d_in[11];
    const float* We2   = (const float*)d_in[12];
    const float* as2   = (const float*)d_in[13];
    const float* ad2   = (const float*)d_in[14];
    const float* ae2   = (const float*)d_in[15];
    const float* b2    = (const float*)d_in[16];
    const float* W3    = (const float*)d_in[17];
    const float* We3   = (const float*)d_in[18];
    const float* as3   = (const float*)d_in[19];
    const float* ad3   = (const float*)d_in[20];
    const float* ae3   = (const float*)d_in[21];
    const float* b3    = (const float*)d_in[22];
    const float* r1_w  = (const float*)d_in[23];
    const float* r1_b  = (const float*)d_in[24];
    const float* r2_w  = (const float*)d_in[25];
    const float* r2_b  = (const float*)d_in[26];
    const float* ffn_w1 = (const float*)d_in[27];
    const float* ffn_b1 = (const float*)d_in[28];
    const float* ffn_w2 = (const float*)d_in[29];
    const float* ffn_b2 = (const float*)d_in[30];
    float* out = (float*)d_out;

    const int* src = eidx;
    const int* dst = eidx + NE;

    bf16 *xh, *xl, *gxh, *gxl, *z1h, *z1l, *z2h, *z2l, *t64h, *t64l;
    bf16 *wfah, *wfal, *wb1h, *wb1l, *wb2h, *wb2l, *w3h, *w3l, *wf1h, *wf1l, *wf2h, *wf2l;
    float *hr, *zself, *h3, *bb1, *bb2;
    cudaGetSymbolAddress((void**)&xh, g_xh);   cudaGetSymbolAddress((void**)&xl, g_xl);
    cudaGetSymbolAddress((void**)&gxh, g_gxh); cudaGetSymbolAddress((void**)&gxl, g_gxl);
    cudaGetSymbolAddress((void**)&hr, g_hr);
    cudaGetSymbolAddress((void**)&z1h, g_z1h); cudaGetSymbolAddress((void**)&z1l, g_z1l);
    cudaGetSymbolAddress((void**)&z2h, g_z2h); cudaGetSymbolAddress((void**)&z2l, g_z2l);
    cudaGetSymbolAddress((void**)&t64h, g_t64h); cudaGetSymbolAddress((void**)&t64l, g_t64l);
    cudaGetSymbolAddress((void**)&zself, g_zself);
    cudaGetSymbolAddress((void**)&h3, g_h3);
    cudaGetSymbolAddress((void**)&wfah, g_wfa_h); cudaGetSymbolAddress((void**)&wfal, g_wfa_l);
    cudaGetSymbolAddress((void**)&wb1h, g_wb1_h); cudaGetSymbolAddress((void**)&wb1l, g_wb1_l);
    cudaGetSymbolAddress((void**)&wb2h, g_wb2_h); cudaGetSymbolAddress((void**)&wb2l, g_wb2_l);
    cudaGetSymbolAddress((void**)&w3h, g_w3_h);   cudaGetSymbolAddress((void**)&w3l, g_w3_l);
    cudaGetSymbolAddress((void**)&wf1h, g_wf1_h); cudaGetSymbolAddress((void**)&wf1l, g_wf1_l);
    cudaGetSymbolAddress((void**)&wf2h, g_wf2_h); cudaGetSymbolAddress((void**)&wf2l, g_wf2_l);
    cudaGetSymbolAddress((void**)&bb1, g_bb1);
    cudaGetSymbolAddress((void**)&bb2, g_bb2);

    cudaFuncSetAttribute(gemm5<EP_RELU, true, false>,
                         cudaFuncAttributeMaxDynamicSharedMemorySize, SMEM_DB);
    cudaFuncSetAttribute(gemm5<EP_NONE, false, true>,
                         cudaFuncAttributeMaxDynamicSharedMemorySize, SMEM_DB);
    cudaFuncSetAttribute(gemm6<EP_GATE, true, false>,
                         cudaFuncAttributeMaxDynamicSharedMemorySize, SMEM2);
    cudaFuncSetAttribute(gemm6<EP_NONE, false, true>,
                         cudaFuncAttributeMaxDynamicSharedMemorySize, SMEM2);

    const int TB = 256;
    const int nbN = (NN + TB - 1) / TB;
    const int nbE = (NE + TB - 1) / TB;
    const int gy = (NN + 127) / 128;

    // launch 1: weight prep for gate + layer1
    packall_kernel<<<(82944 + 255) / 256, 256>>>(fa_w, r1_w, W1, r1_b, r2_b);
    // launch 2: split x
    split_bf_kernel<<<(NN * 128 + 255) / 256, 256>>>(x, xh, xl, NN * 128);
    // launch 3: gate gemm (N=128, gemm6)
    gemm6<EP_GATE, true, false><<<dim3(1, gy), 128, SMEM2>>>(
        xh, xl, wfah, wfal, fa_b, x, nullptr, gxh, gxl, NN, 128, 128);
    // launch 4: layer-1 GEMM (N=512, gemm6)  <-- profiled launch
    gemm6<EP_NONE, false, true><<<dim3(4, gy), 128, SMEM2>>>(
        gxh, gxl, wb1h, wb1l, bb1, nullptr, hr, nullptr, nullptr, NN, 128, 512);

    // CSR build + head constants
    zero_kernel<<<nbN, TB>>>();
    deg_kernel<<<nbE, TB>>>(dst, ea);
    alloc_kernel<<<(NN + 1023) / 1024, 1024>>>();
    csr_kernel<<<nbE, TB>>>(dst);
    ch123_kernel<<<1, 32>>>(We1, ae1, We2, ae2, We3, ae3);

    // remaining weight packs
    packfuseT_kernel<<<(512 * 256 + 255) / 256, 256>>>(r2_w, W2, wb2h, wb2l, 256, 256);
    packT_kernel<<<(64 * 256 + 255) / 256, 256>>>(W3, w3h, w3l, 256, 64);
    packT_kernel<<<(64 * 128 + 255) / 256, 256>>>(ffn_w1, wf1h, wf1l, 128, 64);
    packT_kernel<<<(64 * 64 + 255) / 256, 256>>>(ffn_w2, wf2h, wf2l, 64, 64);

    // ffn path (N=64 -> gemm5)
    gemm5<EP_RELU, true, false><<<dim3(1, gy), 256, SMEM_DB>>>(
        gxh, gxl, wf1h, wf1l, ffn_b1, nullptr, nullptr, t64h, t64l, NN, 128, 64);
    gemm5<EP_NONE, false, true><<<dim3(1, gy), 256, SMEM_DB>>>(
        t64h, t64l, wf2h, wf2l, ffn_b2, nullptr, zself, nullptr, nullptr, NN, 64, 64);

    // layer 1 attention + aggregation
    attn_kernel<4><<<(NN * 4 * 32 + TB - 1) / TB, TB>>>(hr + 256, 512, as1, ad1);
    agg3<4, 64, true, false><<<NN, 256>>>(hr + 256, 512, src, ea, b1, 0, hr, 512,
                                          nullptr, z1h, z1l);

    // layer 2 (gemm6)
    gemm6<EP_NONE, false, true><<<dim3(4, gy), 128, SMEM2>>>(
        z1h, z1l, wb2h, wb2l, bb2, nullptr, hr, nullptr, nullptr, NN, 256, 512);
    attn_kernel<4><<<(NN * 4 * 32 + TB - 1) / TB, TB>>>(hr + 256, 512, as2, ad2);
    agg3<4, 64, true, false><<<NN, 256>>>(hr + 256, 512, src, ea, b2, 4, hr, 512,
                                          nullptr, z2h, z2l);

    // layer 3 (N=64 -> gemm5)
    gemm5<EP_NONE, false, true><<<dim3(1, gy), 256, SMEM_DB>>>(
        z2h, z2l, w3h, w3l, nullptr, nullptr, h3, nullptr, nullptr, NN, 256, 64);
    attn_kernel<1><<<(NN * 32 + TB - 1) / TB, TB>>>(h3, 64, as3, ad3);
    agg3<1, 64, false, true><<<NN, 64>>>(h3, 64, src, ea, b3, 8, zself, 64,
                                         out, nullptr, nullptr);
}

// round 15
// speedup vs baseline: 1.0853x; 1.0569x over previous
#include <cuda_runtime.h>
#include <cuda_bf16.h>
#include <math.h>
#include <stdint.h>

#define NN 50000
#define NE 800000

typedef __nv_bfloat16 bf16;

// ---------------- scratch (device globals) ----------------
__device__ __align__(16) bf16 g_xh[NN * 128], g_xl[NN * 128];
__device__ __align__(16) bf16 g_gxh[NN * 128], g_gxl[NN * 128];
__device__ float g_res[NN * 256];                         // residual half (fp32)
__device__ __align__(16) bf16 g_hb[NN * 256];             // h half (bf16) for gather
__device__ __align__(16) bf16 g_z1h[NN * 256], g_z1l[NN * 256];
__device__ __align__(16) bf16 g_z2h[NN * 256], g_z2l[NN * 256];
__device__ __align__(16) bf16 g_t64h[NN * 64], g_t64l[NN * 64];
__device__ float g_zself[NN * 64];
__device__ float g_h3[NN * 64];
__device__ float g_asrc[NN * 4];
__device__ float g_adst[NN * 4];
__device__ float g_loop[NN];
__device__ float g_easum[NN];
__device__ int   g_deg[NN];
__device__ int   g_rowstart[NN];
__device__ int   g_cursor[NN];
__device__ int   g_csr[NE];
__device__ float g_chv[12];     // [0..3] layer1, [4..7] layer2, [8] layer3
__device__ int   g_total;
// transposed [n][k] k-major bf16 weight splits
__device__ __align__(16) bf16 g_wfa_h[128 * 128], g_wfa_l[128 * 128];
__device__ __align__(16) bf16 g_wb1_h[512 * 128], g_wb1_l[512 * 128];
__device__ __align__(16) bf16 g_wb2_h[512 * 256], g_wb2_l[512 * 256];
__device__ __align__(16) bf16 g_w3_h[64 * 256],  g_w3_l[64 * 256];
__device__ __align__(16) bf16 g_wf1_h[64 * 128], g_wf1_l[64 * 128];
__device__ __align__(16) bf16 g_wf2_h[64 * 64],  g_wf2_l[64 * 64];
__device__ float g_bb1[512], g_bb2[512];

__device__ __forceinline__ float sigf(float x) { return 1.f / (1.f + __expf(-x)); }

__device__ __forceinline__ void bf_split(float x, bf16& h, bf16& l) {
    h = __float2bfloat16(x);
    l = __float2bfloat16(x - __bfloat162float(h));
}

__device__ __forceinline__ void mma_bf16(float* c, const uint32_t* a, const uint32_t* b) {
    asm volatile(
        "mma.sync.aligned.m16n8k16.row.col.f32.bf16.bf16.f32 "
        "{%0,%1,%2,%3}, {%4,%5,%6,%7}, {%8,%9}, {%0,%1,%2,%3};\n"
        : "+f"(c[0]), "+f"(c[1]), "+f"(c[2]), "+f"(c[3])
        : "r"(a[0]), "r"(a[1]), "r"(a[2]), "r"(a[3]), "r"(b[0]), "r"(b[1]));
}

__device__ __forceinline__ void ldsm_x4(uint32_t& r0, uint32_t& r1, uint32_t& r2,
                                        uint32_t& r3, uint32_t addr) {
    asm volatile("ldmatrix.sync.aligned.m8n8.x4.shared.b16 {%0,%1,%2,%3}, [%4];"
                 : "=r"(r0), "=r"(r1), "=r"(r2), "=r"(r3) : "r"(addr));
}

__device__ __forceinline__ void cp16(uint32_t dst, const void* src, int sz) {
    asm volatile("cp.async.cg.shared.global [%0], [%1], 16, %2;\n"
                 :: "r"(dst), "l"(src), "r"(sz));
}
__device__ __forceinline__ void cp_commit() {
    asm volatile("cp.async.commit_group;\n");
}
template <int N>
__device__ __forceinline__ void cp_wait() {
    asm volatile("cp.async.wait_group %0;\n" :: "n"(N));
}

// ---------------- pack / split kernels ----------------
__global__ void split_bf_kernel(const float* __restrict__ s, bf16* __restrict__ dh,
                                bf16* __restrict__ dl, int n) {
    int i = blockIdx.x * blockDim.x + threadIdx.x;
    if (i < n) { bf16 h, l; bf_split(s[i], h, l); dh[i] = h; dl[i] = l; }
}
__global__ void packall_kernel(const float* __restrict__ fa_w,
                               const float* __restrict__ r1_w, const float* __restrict__ W1,
                               const float* __restrict__ r1_b, const float* __restrict__ r2_b) {
    int i = blockIdx.x * blockDim.x + threadIdx.x;
    if (i < 16384) {
        int n = i >> 7, k = i & 127;
        bf16 h, l; bf_split(fa_w[k * 128 + n], h, l);
        g_wfa_h[i] = h; g_wfa_l[i] = l;
    } else if (i < 16384 + 65536) {
        int j = i - 16384;
        int n = j >> 7, k = j & 127;
        float v = (n < 256) ? r1_w[k * 256 + n] : W1[k * 256 + n - 256];
        bf16 h, l; bf_split(v, h, l);
        g_wb1_h[j] = h; g_wb1_l[j] = l;
    } else if (i < 16384 + 65536 + 512) {
        int j = i - 81920;
        g_bb1[j] = (j < 256) ? r1_b[j] : 0.f;
    } else if (i < 16384 + 65536 + 1024) {
        int j = i - 82432;
        g_bb2[j] = (j < 256) ? r2_b[j] : 0.f;
    }
}
__global__ void packT_kernel(const float* __restrict__ W, bf16* __restrict__ th,
                             bf16* __restrict__ tl, int K_, int N_) {
    int i = blockIdx.x * blockDim.x + threadIdx.x;
    if (i < K_ * N_) {
        int n = i / K_, k = i % K_;
        bf16 h, l; bf_split(W[k * N_ + n], h, l);
        th[i] = h; tl[i] = l;
    }
}
__global__ void packfuseT_kernel(const float* __restrict__ A_, const float* __restrict__ B_,
                                 bf16* __restrict__ th, bf16* __restrict__ tl,
                                 int K_, int half) {
    int i = blockIdx.x * blockDim.x + threadIdx.x;
    if (i < 2 * half * K_) {
        int n = i / K_, k = i % K_;
        float v = (n < half) ? A_[k * half + n] : B_[k * half + n - half];
        bf16 h, l; bf_split(v, h, l);
        th[i] = h; tl[i] = l;
    }
}
__global__ void ch123_kernel(const float* __restrict__ We1, const float* __restrict__ ae1,
                             const float* __restrict__ We2, const float* __restrict__ ae2,
                             const float* __restrict__ We3, const float* __restrict__ ae3) {
    int t = threadIdx.x;
    if (t < 4) {
        float s = 0.f;
        for (int c = 0; c < 64; c++) s += We1[t * 64 + c] * ae1[t * 64 + c];
        g_chv[t] = s;
    } else if (t < 8) {
        int h = t - 4;
        float s = 0.f;
        for (int c = 0; c < 64; c++) s += We2[h * 64 + c] * ae2[h * 64 + c];
        g_chv[4 + h] = s;
    } else if (t == 8) {
        float s = 0.f;
        for (int c = 0; c < 64; c++) s += We3[c] * ae3[c];
        g_chv[8] = s;
    }
}

#define EP_NONE 0
#define EP_GATE 1
#define EP_RELU 2

// ---------------- gemm5: bf16x3 m16n8k16, BM=128 BN=64 BK=32 (N=64 cases) --
#define SMEM_DB (15360 * 4)

template <int EP, bool SPLITOUT, bool WRITEC>
__global__ __launch_bounds__(256) void gemm5(
    const bf16* __restrict__ Agh, const bf16* __restrict__ Agl,
    const bf16* __restrict__ Bgh, const bf16* __restrict__ Bgl,
    const float* __restrict__ bias, const float* __restrict__ gateA,
    float* __restrict__ C, bf16* __restrict__ Ch, bf16* __restrict__ Cl,
    int M, int K, int N) {
    extern __shared__ uint32_t smu[];
    const int bm = blockIdx.y * 128, bn = blockIdx.x * 64;
    const int tid = threadIdx.x, lane = tid & 31, wid = tid >> 5;
    const int wm = wid >> 1, wn = wid & 1;
    const int lg = lane >> 2, lt = lane & 3;
    const int arow = tid >> 2, q = tid & 3;

    float acc[2][4][4];
#pragma unroll
    for (int mt = 0; mt < 2; mt++)
#pragma unroll
        for (int nt = 0; nt < 4; nt++)
#pragma unroll
            for (int j = 0; j < 4; j++) acc[mt][nt][j] = 0.f;

    uint4 rA[2][2], rB[2];
    const uint4 z16 = make_uint4(0u, 0u, 0u, 0u);

#pragma unroll
    for (int t = 0; t < 2; t++) {
        int grow = bm + arow + t * 64;
        if (grow < M) {
            rA[t][0] = ((const uint4*)(Agh + (size_t)grow * K))[q];
            rA[t][1] = ((const uint4*)(Agl + (size_t)grow * K))[q];
        } else { rA[t][0] = z16; rA[t][1] = z16; }
    }
    rB[0] = ((const uint4*)(Bgh + (size_t)(bn + arow) * K))[q];
    rB[1] = ((const uint4*)(Bgl + (size_t)(bn + arow) * K))[q];

    int p = 0;
    {
#pragma unroll
        for (int t = 0; t < 2; t++) {
            int row = arow + t * 64;
#pragma unroll
            for (int s = 0; s < 2; s++) {
                uint32_t* d = smu + s * 2560 + row * 20 + q * 4;
                uint4 v = rA[t][s];
                d[0] = v.x; d[1] = v.y; d[2] = v.z; d[3] = v.w;
            }
        }
#pragma unroll
        for (int s = 0; s < 2; s++) {
            uint32_t* d = smu + 10240 + s * 1280 + arow * 20 + q * 4;
            uint4 v = rB[s];
            d[0] = v.x; d[1] = v.y; d[2] = v.z; d[3] = v.w;
        }
    }
    __syncthreads();

    for (int k0 = 0; k0 < K; k0 += 32) {
        const bool more = (k0 + 32 < K);
        if (more) {
            int kn = k0 + 32;
#pragma unroll
            for (int t = 0; t < 2; t++) {
                int grow = bm + arow + t * 64;
                if (grow < M) {
                    rA[t][0] = ((const uint4*)(Agh + (size_t)grow * K + kn))[q];
                    rA[t][1] = ((const uint4*)(Agl + (size_t)grow * K + kn))[q];
                } else { rA[t][0] = z16; rA[t][1] = z16; }
            }
            rB[0] = ((const uint4*)(Bgh + (size_t)(bn + arow) * K + kn))[q];
            rB[1] = ((const uint4*)(Bgl + (size_t)(bn + arow) * K + kn))[q];
        }
        {
            const uint32_t* Ah = smu + (p * 2 + 0) * 2560;
            const uint32_t* Al = smu + (p * 2 + 1) * 2560;
            const uint32_t* Bh = smu + 10240 + (p * 2 + 0) * 1280;
            const uint32_t* Bl = smu + 10240 + (p * 2 + 1) * 1280;
#pragma unroll
            for (int ks = 0; ks < 2; ks++) {
                const int kp = ks * 8 + lt;
                uint32_t ah[2][4], al[2][4];
#pragma unroll
                for (int mt = 0; mt < 2; mt++) {
                    int r = wm * 32 + mt * 16 + lg;
                    ah[mt][0] = Ah[r * 20 + kp];
                    ah[mt][1] = Ah[(r + 8) * 20 + kp];
                    ah[mt][2] = Ah[r * 20 + kp + 4];
                    ah[mt][3] = Ah[(r + 8) * 20 + kp + 4];
                    al[mt][0] = Al[r * 20 + kp];
                    al[mt][1] = Al[(r + 8) * 20 + kp];
                    al[mt][2] = Al[r * 20 + kp + 4];
                    al[mt][3] = Al[(r + 8) * 20 + kp + 4];
                }
#pragma unroll
                for (int nt = 0; nt < 4; nt++) {
                    int c = wn * 32 + nt * 8 + lg;
                    uint32_t bh[2], bl2[2];
                    bh[0] = Bh[c * 20 + kp];
                    bh[1] = Bh[c * 20 + kp + 4];
                    bl2[0] = Bl[c * 20 + kp];
                    bl2[1] = Bl[c * 20 + kp + 4];
#pragma unroll
                    for (int mt = 0; mt < 2; mt++) {
                        mma_bf16(acc[mt][nt], ah[mt], bh);
                        mma_bf16(acc[mt][nt], al[mt], bh);
                        mma_bf16(acc[mt][nt], ah[mt], bl2);
                    }
                }
            }
        }
        if (more) {
            int pb = p ^ 1;
#pragma unroll
            for (int t = 0; t < 2; t++) {
                int row = arow + t * 64;
#pragma unroll
                for (int s = 0; s < 2; s++) {
                    uint32_t* d = smu + (pb * 2 + s) * 2560 + row * 20 + q * 4;
                    uint4 v = rA[t][s];
                    d[0] = v.x; d[1] = v.y; d[2] = v.z; d[3] = v.w;
                }
            }
#pragma unroll
            for (int s = 0; s < 2; s++) {
                uint32_t* d = smu + 10240 + (pb * 2 + s) * 1280 + arow * 20 + q * 4;
                uint4 v = rB[s];
                d[0] = v.x; d[1] = v.y; d[2] = v.z; d[3] = v.w;
            }
            __syncthreads();
            p = pb;
        }
    }
#pragma unroll
    for (int mt = 0; mt < 2; mt++) {
        int r0 = bm + wm * 32 + mt * 16 + lg;
#pragma unroll
        for (int nt = 0; nt < 4; nt++) {
            int c0 = bn + wn * 32 + nt * 8 + lt * 2;
#pragma unroll
            for (int j = 0; j < 4; j++) {
                int row = r0 + (j >> 1) * 8;
                int col = c0 + (j & 1);
                if (row >= M) continue;
                float v = acc[mt][nt][j] + (bias ? bias[col] : 0.f);
                if (EP == EP_GATE) v = gateA[(size_t)row * K + col] * sigf(v);
                else if (EP == EP_RELU) v = fmaxf(v, 0.f);
                size_t idx = (size_t)row * N + col;
                if (WRITEC) C[idx] = v;
                if (SPLITOUT) {
                    bf16 h, l; bf_split(v, h, l);
                    Ch[idx] = h; Cl[idx] = l;
                }
            }
        }
    }
}

// ---------------- gemm6: BM=128 BN=128, 4 warps 64x64, cp.async + ldmatrix --
// HB16: res half (col<256) -> fp32 C[row*256+col]; h half -> bf16 Hb[row*256+col-256]
#define SMEM2 (20480 * 4)

template <int EP, bool SPLITOUT, bool WRITEC, bool HB16>
__global__ __launch_bounds__(128) void gemm6(
    const bf16* __restrict__ Agh, const bf16* __restrict__ Agl,
    const bf16* __restrict__ Bgh, const bf16* __restrict__ Bgl,
    const float* __restrict__ bias, const float* __restrict__ gateA,
    float* __restrict__ C, bf16* __restrict__ Ch, bf16* __restrict__ Cl,
    bf16* __restrict__ Hb,
    int M, int K, int N) {
    extern __shared__ uint32_t smu[];
    const int bm = blockIdx.y * 128, bn = blockIdx.x * 128;
    const int tid = threadIdx.x, lane = tid & 31, wid = tid >> 5;
    const int wm = wid >> 1, wn = wid & 1;
    const int lg = lane >> 2, lt = lane & 3;
    const uint32_t smb = (uint32_t)__cvta_generic_to_shared(smu);

    const int lane7 = lane & 7;
    const int aoff = (wm * 64 + lane7 + ((lane >> 3) & 1) * 8) * 20 + ((lane >> 4) & 1) * 4;
    const int boff = (wn * 64 + lane7 + ((lane >> 4) & 1) * 8) * 20 + ((lane >> 3) & 1) * 4;

    float acc[4][8][4];
#pragma unroll
    for (int mt = 0; mt < 4; mt++)
#pragma unroll
        for (int nt = 0; nt < 8; nt++)
#pragma unroll
            for (int j = 0; j < 4; j++) acc[mt][nt][j] = 0.f;

    auto issue = [&](int p, int k0) {
#pragma unroll
        for (int i = 0; i < 4; i++) {
            int idx = tid + i * 128;
            int row = idx >> 2, q = idx & 3;
            int grow = bm + row;
            int sz = (grow < M) ? 16 : 0;
            int cg = (grow < M) ? grow : (M - 1);
            cp16(smb + (((p * 2 + 0) * 2560 + row * 20 + q * 4) << 2),
                 Agh + (size_t)cg * K + k0 + q * 8, sz);
            cp16(smb + (((p * 2 + 1) * 2560 + row * 20 + q * 4) << 2),
                 Agl + (size_t)cg * K + k0 + q * 8, sz);
            cp16(smb + ((10240 + (p * 2 + 0) * 2560 + row * 20 + q * 4) << 2),
                 Bgh + (size_t)(bn + row) * K + k0 + q * 8, 16);
            cp16(smb + ((10240 + (p * 2 + 1) * 2560 + row * 20 + q * 4) << 2),
                 Bgl + (size_t)(bn + row) * K + k0 + q * 8, 16);
        }
        cp_commit();
    };

    issue(0, 0);
    int p = 0;
    for (int k0 = 0; k0 < K; k0 += 32) {
        const bool more = (k0 + 32 < K);
        if (more) issue(p ^ 1, k0 + 32);
        if (more) cp_wait<1>(); else cp_wait<0>();
        __syncthreads();
        {
            const uint32_t baseAh = smb + (((p * 2 + 0) * 2560 + aoff) << 2);
            const uint32_t baseAl = smb + (((p * 2 + 1) * 2560 + aoff) << 2);
            const uint32_t baseBh = smb + ((10240 + (p * 2 + 0) * 2560 + boff) << 2);
            const uint32_t baseBl = smb + ((10240 + (p * 2 + 1) * 2560 + boff) << 2);
#pragma unroll
            for (int ks = 0; ks < 2; ks++) {
                uint32_t ah[4][4], al[4][4];
#pragma unroll
                for (int mt = 0; mt < 4; mt++) {
                    ldsm_x4(ah[mt][0], ah[mt][1], ah[mt][2], ah[mt][3],
                            baseAh + ((mt * 320 + ks * 8) << 2));
                    ldsm_x4(al[mt][0], al[mt][1], al[mt][2], al[mt][3],
                            baseAl + ((mt * 320 + ks * 8) << 2));
                }
#pragma unroll
                for (int j = 0; j < 4; j++) {
                    uint32_t bh0[2], bh1[2], bl0[2], bl1[2];
                    ldsm_x4(bh0[0], bh0[1], bh1[0], bh1[1],
                            baseBh + ((j * 320 + ks * 8) << 2));
                    ldsm_x4(bl0[0], bl0[1], bl1[0], bl1[1],
                            baseBl + ((j * 320 + ks * 8) << 2));
#pragma unroll
                    for (int mt = 0; mt < 4; mt++) {
                        mma_bf16(acc[mt][2 * j + 0], ah[mt], bh0);
                        mma_bf16(acc[mt][2 * j + 0], al[mt], bh0);
                        mma_bf16(acc[mt][2 * j + 0], ah[mt], bl0);
                        mma_bf16(acc[mt][2 * j + 1], ah[mt], bh1);
                        mma_bf16(acc[mt][2 * j + 1], al[mt], bh1);
                        mma_bf16(acc[mt][2 * j + 1], ah[mt], bl1);
                    }
                }
            }
        }
        __syncthreads();
        p ^= 1;
    }
    // epilogue
#pragma unroll
    for (int mt = 0; mt < 4; mt++) {
        int r0 = bm + wm * 64 + mt * 16 + lg;
#pragma unroll
        for (int nt = 0; nt < 8; nt++) {
            int c0 = bn + wn * 64 + nt * 8 + lt * 2;
            if (HB16) {
#pragma unroll
                for (int half = 0; half < 2; half++) {
                    int row = r0 + half * 8;
                    if (row >= M) continue;
                    float v0 = acc[mt][nt][half * 2 + 0] + bias[c0];
                    float v1 = acc[mt][nt][half * 2 + 1] + bias[c0 + 1];
                    if (c0 < 256) {
                        C[(size_t)row * 256 + c0] = v0;
                        C[(size_t)row * 256 + c0 + 1] = v1;
                    } else {
                        __nv_bfloat162 pr;
                        pr.x = __float2bfloat16(v0);
                        pr.y = __float2bfloat16(v1);
                        *(__nv_bfloat162*)&Hb[(size_t)row * 256 + c0 - 256] = pr;
                    }
                }
            } else {
#pragma unroll
                for (int j = 0; j < 4; j++) {
                    int row = r0 + (j >> 1) * 8;
                    int col = c0 + (j & 1);
                    if (row >= M) continue;
                    float v = acc[mt][nt][j] + (bias ? bias[col] : 0.f);
                    if (EP == EP_GATE) v = gateA[(size_t)row * K + col] * sigf(v);
                    else if (EP == EP_RELU) v = fmaxf(v, 0.f);
                    size_t idx = (size_t)row * N + col;
                    if (WRITEC) C[idx] = v;
                    if (SPLITOUT) {
                        bf16 h, l; bf_split(v, h, l);
                        Ch[idx] = h; Cl[idx] = l;
                    }
                }
            }
        }
    }
}

// ---------------- CSR build ----------------
__global__ void zero_kernel() {
    int i = blockIdx.x * blockDim.x + threadIdx.x;
    if (i < NN) { g_deg[i] = 0; g_cursor[i] = 0; g_easum[i] = 0.f; }
    if (i == 0) g_total = 0;
}
__global__ void deg_kernel(const int* __restrict__ dst, const float* __restrict__ ea) {
    int e = blockIdx.x * blockDim.x + threadIdx.x;
    if (e < NE) {
        int d = dst[e];
        atomicAdd(&g_deg[d], 1);
        atomicAdd(&g_easum[d], ea[e]);
    }
}
__global__ void alloc_kernel() {
    __shared__ int s[1024];
    __shared__ int base;
    int tid = threadIdx.x;
    int i = blockIdx.x * 1024 + tid;
    int v = (i < NN) ? g_deg[i] : 0;
    s[tid] = v;
    __syncthreads();
    for (int off = 1; off < 1024; off <<= 1) {
        int t = (tid >= off) ? s[tid - off] : 0;
        __syncthreads();
        s[tid] += t;
        __syncthreads();
    }
    int incl = s[tid];
    if (tid == 1023) base = atomicAdd(&g_total, s[1023]);
    __syncthreads();
    if (i < NN) {
        g_rowstart[i] = base + incl - v;
        g_loop[i] = g_easum[i] / fmaxf((float)v, 1.f);
    }
}
__global__ void csr_kernel(const int* __restrict__ dst) {
    int e = blockIdx.x * blockDim.x + threadIdx.x;
    if (e < NE) {
        int d = dst[e];
        int pos = atomicAdd(&g_cursor[d], 1);
        g_csr[g_rowstart[d] + pos] = e;
    }
}

// ---------------- attention coefficients ----------------
template <int H, typename T>
__global__ void attn_kernel(const T* __restrict__ hbuf, int stride,
                            const float* __restrict__ a_s, const float* __restrict__ a_d) {
    int w = (blockIdx.x * blockDim.x + threadIdx.x) >> 5;
    int lane = threadIdx.x & 31;
    if (w >= NN * H) return;
    int n = w / H, hh = w % H;
    const T* hr = hbuf + (size_t)n * stride + hh * 64;
    float as0 = a_s[hh * 64 + lane], as1 = a_s[hh * 64 + lane + 32];
    float ad0 = a_d[hh * 64 + lane], ad1 = a_d[hh * 64 + lane + 32];
    float h0 = (float)hr[lane], h1 = (float)hr[lane + 32];
    float vs = h0 * as0 + h1 * as1;
    float vd = h0 * ad0 + h1 * ad1;
#pragma unroll
    for (int off = 16; off > 0; off >>= 1) {
        vs += __shfl_down_sync(0xffffffffu, vs, off);
        vd += __shfl_down_sync(0xffffffffu, vd, off);
    }
    if (lane == 0) { g_asrc[w] = vs; g_adst[w] = vd; }
}

// ---------------- per-node softmax aggregation (single pass, no max) -------
template <int H, int C, bool SPLIT, bool WRITEO, typename GT>
__global__ void agg3(const GT* __restrict__ hbuf, int hstride,
                     const int* __restrict__ src, const float* __restrict__ ea,
                     const float* __restrict__ bias, int choff,
                     const float* __restrict__ resid, int rstride,
                     float* __restrict__ out, bf16* __restrict__ outh,
                     bf16* __restrict__ outl) {
    constexpr int OUT = H * C;
    constexpr int CH = 64;
    __shared__ float s_alpha[CH * H];
    __shared__ int s_sid[CH];
    __shared__ float s_red[2 * H];

    const int n = blockIdx.x;
    const int tid = threadIdx.x;
    const int deg = g_deg[n];
    const int rs = g_rowstart[n];
    const int T = deg + 1;
    const float loopv = g_loop[n];

    float adst[H], chh[H], zloc[H];
#pragma unroll
    for (int h = 0; h < H; h++) zloc[h] = 0.f;
    if (tid < CH) {
#pragma unroll
        for (int h = 0; h < H; h++) { adst[h] = g_adst[n * H + h]; chh[h] = g_chv[choff + h]; }
    }

    const int hh = tid / C;
    float acc = 0.f;
    for (int base = 0; base < T; base += CH) {
        int i = base + tid;
        if (tid < CH && i < T) {
            int sN; float eav;
            if (i < deg) { int e = g_csr[rs + i]; sN = src[e]; eav = ea[e]; }
            else { sN = n; eav = loopv; }
#pragma unroll
            for (int h = 0; h < H; h++) {
                float v = g_asrc[sN * H + h] + adst[h] + chh[h] * eav;
                v = (v >= 0.f) ? v : 0.2f * v;
                float ex = __expf(v);
                s_alpha[tid * H + h] = ex;
                zloc[h] += ex;
            }
            s_sid[tid] = sN;
        }
        __syncthreads();
        int lim = min(CH, T - base);
        for (int j = 0; j < lim; j++)
            acc += s_alpha[j * H + hh] * (float)hbuf[(size_t)s_sid[j] * hstride + tid];
        __syncthreads();
    }
    if (tid < CH) {
#pragma unroll
        for (int off = 16; off > 0; off >>= 1)
#pragma unroll
            for (int h = 0; h < H; h++)
                zloc[h] += __shfl_xor_sync(0xffffffffu, zloc[h], off);
        if ((tid & 31) == 0) {
#pragma unroll
            for (int h = 0; h < H; h++) s_red[(tid >> 5) * H + h] = zloc[h];
        }
    }
    __syncthreads();
    float z = s_red[hh] + s_red[H + hh];
    float v = acc / z + bias[tid];
    v = (v >= 0.f) ? v : 0.01f * v;
    v += resid[(size_t)n * rstride + tid];
    size_t idx = (size_t)n * OUT + tid;
    if (WRITEO) out[idx] = v;
    if (SPLIT) {
        bf16 h, l; bf_split(v, h, l);
        outh[idx] = h; outl[idx] = l;
    }
}

// ---------------- driver ----------------
extern "C" void kernel_launch(void* const* d_in, const int* in_sizes, int n_in,
                              void* d_out, int out_size) {
    const float* x     = (const float*)d_in[0];
    const int*   eidx  = (const int*)d_in[1];
    const float* ea    = (const float*)d_in[2];
    const float* fa_w  = (const float*)d_in[3];
    const float* fa_b  = (const float*)d_in[4];
    const float* W1    = (const float*)d_in[5];
    const float* We1   = (const float*)d_in[6];
    const float* as1   = (const float*)d_in[7];
    const float* ad1   = (const float*)d_in[8];
    const float* ae1   = (const float*)d_in[9];
    const float* b1    = (const float*)d_in[10];
    const float* W2    = (const float*)d_in[11];
    const float* We2   = (const float*)d_in[12];
    const float* as2   = (const float*)d_in[13];
    const float* ad2   = (const float*)d_in[14];
    const float* ae2   = (const float*)d_in[15];
    const float* b2    = (const float*)d_in[16];
    const float* W3    = (const float*)d_in[17];
    const float* We3   = (const float*)d_in[18];
    const float* as3   = (const float*)d_in[19];
    const float* ad3   = (const float*)d_in[20];
    const float* ae3   = (const float*)d_in[21];
    const float* b3    = (const float*)d_in[22];
    const float* r1_w  = (const float*)d_in[23];
    const float* r1_b  = (const float*)d_in[24];
    const float* r2_w  = (const float*)d_in[25];
    const float* r2_b  = (const float*)d_in[26];
    const float* ffn_w1 = (const float*)d_in[27];
    const float* ffn_b1 = (const float*)d_in[28];
    const float* ffn_w2 = (const float*)d_in[29];
    const float* ffn_b2 = (const float*)d_in[30];
    float* out = (float*)d_out;

    const int* src = eidx;
    const int* dst = eidx + NE;

    bf16 *xh, *xl, *gxh, *gxl, *hb, *z1h, *z1l, *z2h, *z2l, *t64h, *t64l;
    bf16 *wfah, *wfal, *wb1h, *wb1l, *wb2h, *wb2l, *w3h, *w3l, *wf1h, *wf1l, *wf2h, *wf2l;
    float *res, *zself, *h3, *bb1, *bb2;
    cudaGetSymbolAddress((void**)&xh, g_xh);   cudaGetSymbolAddress((void**)&xl, g_xl);
    cudaGetSymbolAddress((void**)&gxh, g_gxh); cudaGetSymbolAddress((void**)&gxl, g_gxl);
    cudaGetSymbolAddress((void**)&res, g_res);
    cudaGetSymbolAddress((void**)&hb, g_hb);
    cudaGetSymbolAddress((void**)&z1h, g_z1h); cudaGetSymbolAddress((void**)&z1l, g_z1l);
    cudaGetSymbolAddress((void**)&z2h, g_z2h); cudaGetSymbolAddress((void**)&z2l, g_z2l);
    cudaGetSymbolAddress((void**)&t64h, g_t64h); cudaGetSymbolAddress((void**)&t64l, g_t64l);
    cudaGetSymbolAddress((void**)&zself, g_zself);
    cudaGetSymbolAddress((void**)&h3, g_h3);
    cudaGetSymbolAddress((void**)&wfah, g_wfa_h); cudaGetSymbolAddress((void**)&wfal, g_wfa_l);
    cudaGetSymbolAddress((void**)&wb1h, g_wb1_h); cudaGetSymbolAddress((void**)&wb1l, g_wb1_l);
    cudaGetSymbolAddress((void**)&wb2h, g_wb2_h); cudaGetSymbolAddress((void**)&wb2l, g_wb2_l);
    cudaGetSymbolAddress((void**)&w3h, g_w3_h);   cudaGetSymbolAddress((void**)&w3l, g_w3_l);
    cudaGetSymbolAddress((void**)&wf1h, g_wf1_h); cudaGetSymbolAddress((void**)&wf1l, g_wf1_l);
    cudaGetSymbolAddress((void**)&wf2h, g_wf2_h); cudaGetSymbolAddress((void**)&wf2l, g_wf2_l);
    cudaGetSymbolAddress((void**)&bb1, g_bb1);
    cudaGetSymbolAddress((void**)&bb2, g_bb2);

    cudaFuncSetAttribute(gemm5<EP_RELU, true, false>,
                         cudaFuncAttributeMaxDynamicSharedMemorySize, SMEM_DB);
    cudaFuncSetAttribute(gemm5<EP_NONE, false, true>,
                         cudaFuncAttributeMaxDynamicSharedMemorySize, SMEM_DB);
    cudaFuncSetAttribute(gemm6<EP_GATE, true, false, false>,
                         cudaFuncAttributeMaxDynamicSharedMemorySize, SMEM2);
    cudaFuncSetAttribute(gemm6<EP_NONE, false, true, true>,
                         cudaFuncAttributeMaxDynamicSharedMemorySize, SMEM2);

    const int TB = 256;
    const int nbN = (NN + TB - 1) / TB;
    const int nbE = (NE + TB - 1) / TB;
    const int gy = (NN + 127) / 128;

    // launch 1: weight prep for gate + layer1
    packall_kernel<<<(82944 + 255) / 256, 256>>>(fa_w, r1_w, W1, r1_b, r2_b);
    // launch 2: split x
    split_bf_kernel<<<(NN * 128 + 255) / 256, 256>>>(x, xh, xl, NN * 128);
    // launch 3: gate gemm (N=128, gemm6)
    gemm6<EP_GATE, true, false, false><<<dim3(1, gy), 128, SMEM2>>>(
        xh, xl, wfah, wfal, fa_b, x, nullptr, gxh, gxl, nullptr, NN, 128, 128);
    // launch 4: layer-1 GEMM (N=512, gemm6 HB16)  <-- profiled launch
    gemm6<EP_NONE, false, true, true><<<dim3(4, gy), 128, SMEM2>>>(
        gxh, gxl, wb1h, wb1l, bb1, nullptr, res, nullptr, nullptr, hb, NN, 128, 512);

    // CSR build + head constants
    zero_kernel<<<nbN, TB>>>();
    deg_kernel<<<nbE, TB>>>(dst, ea);
    alloc_kernel<<<(NN + 1023) / 1024, 1024>>>();
    csr_kernel<<<nbE, TB>>>(dst);
    ch123_kernel<<<1, 32>>>(We1, ae1, We2, ae2, We3, ae3);

    // remaining weight packs
    packfuseT_kernel<<<(512 * 256 + 255) / 256, 256>>>(r2_w, W2, wb2h, wb2l, 256, 256);
    packT_kernel<<<(64 * 256 + 255) / 256, 256>>>(W3, w3h, w3l, 256, 64);
    packT_kernel<<<(64 * 128 + 255) / 256, 256>>>(ffn_w1, wf1h, wf1l, 128, 64);
    packT_kernel<<<(64 * 64 + 255) / 256, 256>>>(ffn_w2, wf2h, wf2l, 64, 64);

    // ffn path (N=64 -> gemm5)
    gemm5<EP_RELU, true, false><<<dim3(1, gy), 256, SMEM_DB>>>(
        gxh, gxl, wf1h, wf1l, ffn_b1, nullptr, nullptr, t64h, t64l, NN, 128, 64);
    gemm5<EP_NONE, false, true><<<dim3(1, gy), 256, SMEM_DB>>>(
        t64h, t64l, wf2h, wf2l, ffn_b2, nullptr, zself, nullptr, nullptr, NN, 64, 64);

    // layer 1 attention + aggregation (bf16 h)
    attn_kernel<4, bf16><<<(NN * 4 * 32 + TB - 1) / TB, TB>>>(hb, 256, as1, ad1);
    agg3<4, 64, true, false, bf16><<<NN, 256>>>(hb, 256, src, ea, b1, 0, res, 256,
                                                nullptr, z1h, z1l);

    // layer 2 (gemm6 HB16)
    gemm6<EP_NONE, false, true, true><<<dim3(4, gy), 128, SMEM2>>>(
        z1h, z1l, wb2h, wb2l, bb2, nullptr, res, nullptr, nullptr, hb, NN, 256, 512);
    attn_kernel<4, bf16><<<(NN * 4 * 32 + TB - 1) / TB, TB>>>(hb, 256, as2, ad2);
    agg3<4, 64, true, false, bf16><<<NN, 256>>>(hb, 256, src, ea, b2, 4, res, 256,
                                                nullptr, z2h, z2l);

    // layer 3 (N=64 -> gemm5, fp32 path)
    gemm5<EP_NONE, false, true><<<dim3(1, gy), 256, SMEM_DB>>>(
        z2h, z2l, w3h, w3l, nullptr, nullptr, h3, nullptr, nullptr, NN, 256, 64);
    attn_kernel<1, float><<<(NN * 32 + TB - 1) / TB, TB>>>(h3, 64, as3, ad3);
    agg3<1, 64, false, true, float><<<NN, 64>>>(h3, 64, src, ea, b3, 8, zself, 64,
                                                out, nullptr, nullptr);
}

// round 16
// speedup vs baseline: 1.1101x; 1.0229x over previous
#include <cuda_runtime.h>
#include <cuda_bf16.h>
#include <math.h>
#include <stdint.h>

#define NN 50000
#define NE 800000

typedef __nv_bfloat16 bf16;

// ---------------- scratch (device globals) ----------------
__device__ __align__(16) bf16 g_xh[NN * 128], g_xl[NN * 128];
__device__ __align__(16) bf16 g_gxh[NN * 128], g_gxl[NN * 128];
__device__ float g_res[NN * 256];                         // residual half (fp32)
__device__ __align__(16) bf16 g_hb[NN * 256];             // h half (bf16) for gather
__device__ __align__(16) bf16 g_z1h[NN * 256], g_z1l[NN * 256];
__device__ __align__(16) bf16 g_z2h[NN * 256], g_z2l[NN * 256];
__device__ __align__(16) bf16 g_t64h[NN * 64], g_t64l[NN * 64];
__device__ float g_zself[NN * 64];
__device__ float g_h3[NN * 64];
__device__ float g_asrc[NN * 4];
__device__ float g_adst[NN * 4];
__device__ float g_loop[NN];
__device__ float g_easum[NN];
__device__ int   g_deg[NN];
__device__ int   g_rowstart[NN];
__device__ int   g_cursor[NN];
__device__ int   g_csr_src[NE];
__device__ float g_csr_ea[NE];
__device__ float g_chv[12];     // [0..3] layer1, [4..7] layer2, [8] layer3
__device__ int   g_total;
// transposed [n][k] k-major bf16 weight splits
__device__ __align__(16) bf16 g_wfa_h[128 * 128], g_wfa_l[128 * 128];
__device__ __align__(16) bf16 g_wb1_h[512 * 128], g_wb1_l[512 * 128];
__device__ __align__(16) bf16 g_wb2_h[512 * 256], g_wb2_l[512 * 256];
__device__ __align__(16) bf16 g_w3_h[64 * 256],  g_w3_l[64 * 256];
__device__ __align__(16) bf16 g_wf1_h[64 * 128], g_wf1_l[64 * 128];
__device__ __align__(16) bf16 g_wf2_h[64 * 64],  g_wf2_l[64 * 64];
__device__ float g_bb1[512], g_bb2[512];

__device__ __forceinline__ float sigf(float x) { return 1.f / (1.f + __expf(-x)); }

__device__ __forceinline__ void bf_split(float x, bf16& h, bf16& l) {
    h = __float2bfloat16(x);
    l = __float2bfloat16(x - __bfloat162float(h));
}

__device__ __forceinline__ void mma_bf16(float* c, const uint32_t* a, const uint32_t* b) {
    asm volatile(
        "mma.sync.aligned.m16n8k16.row.col.f32.bf16.bf16.f32 "
        "{%0,%1,%2,%3}, {%4,%5,%6,%7}, {%8,%9}, {%0,%1,%2,%3};\n"
        : "+f"(c[0]), "+f"(c[1]), "+f"(c[2]), "+f"(c[3])
        : "r"(a[0]), "r"(a[1]), "r"(a[2]), "r"(a[3]), "r"(b[0]), "r"(b[1]));
}

__device__ __forceinline__ void ldsm_x4(uint32_t& r0, uint32_t& r1, uint32_t& r2,
                                        uint32_t& r3, uint32_t addr) {
    asm volatile("ldmatrix.sync.aligned.m8n8.x4.shared.b16 {%0,%1,%2,%3}, [%4];"
                 : "=r"(r0), "=r"(r1), "=r"(r2), "=r"(r3) : "r"(addr));
}

__device__ __forceinline__ void cp16(uint32_t dst, const void* src, int sz) {
    asm volatile("cp.async.cg.shared.global [%0], [%1], 16, %2;\n"
                 :: "r"(dst), "l"(src), "r"(sz));
}
__device__ __forceinline__ void cp_commit() {
    asm volatile("cp.async.commit_group;\n");
}
template <int N>
__device__ __forceinline__ void cp_wait() {
    asm volatile("cp.async.wait_group %0;\n" :: "n"(N));
}

// ---------------- pack / split kernels ----------------
__global__ void split_bf_kernel(const float* __restrict__ s, bf16* __restrict__ dh,
                                bf16* __restrict__ dl, int n) {
    int i = blockIdx.x * blockDim.x + threadIdx.x;
    if (i < n) { bf16 h, l; bf_split(s[i], h, l); dh[i] = h; dl[i] = l; }
}
__global__ void packall_kernel(const float* __restrict__ fa_w,
                               const float* __restrict__ r1_w, const float* __restrict__ W1,
                               const float* __restrict__ r1_b, const float* __restrict__ r2_b) {
    int i = blockIdx.x * blockDim.x + threadIdx.x;
    if (i < 16384) {
        int n = i >> 7, k = i & 127;
        bf16 h, l; bf_split(fa_w[k * 128 + n], h, l);
        g_wfa_h[i] = h; g_wfa_l[i] = l;
    } else if (i < 16384 + 65536) {
        int j = i - 16384;
        int n = j >> 7, k = j & 127;
        float v = (n < 256) ? r1_w[k * 256 + n] : W1[k * 256 + n - 256];
        bf16 h, l; bf_split(v, h, l);
        g_wb1_h[j] = h; g_wb1_l[j] = l;
    } else if (i < 16384 + 65536 + 512) {
        int j = i - 81920;
        g_bb1[j] = (j < 256) ? r1_b[j] : 0.f;
    } else if (i < 16384 + 65536 + 1024) {
        int j = i - 82432;
        g_bb2[j] = (j < 256) ? r2_b[j] : 0.f;
    }
}
__global__ void packT_kernel(const float* __restrict__ W, bf16* __restrict__ th,
                             bf16* __restrict__ tl, int K_, int N_) {
    int i = blockIdx.x * blockDim.x + threadIdx.x;
    if (i < K_ * N_) {
        int n = i / K_, k = i % K_;
        bf16 h, l; bf_split(W[k * N_ + n], h, l);
        th[i] = h; tl[i] = l;
    }
}
__global__ void packfuseT_kernel(const float* __restrict__ A_, const float* __restrict__ B_,
                                 bf16* __restrict__ th, bf16* __restrict__ tl,
                                 int K_, int half) {
    int i = blockIdx.x * blockDim.x + threadIdx.x;
    if (i < 2 * half * K_) {
        int n = i / K_, k = i % K_;
        float v = (n < half) ? A_[k * half + n] : B_[k * half + n - half];
        bf16 h, l; bf_split(v, h, l);
        th[i] = h; tl[i] = l;
    }
}
__global__ void ch123_kernel(const float* __restrict__ We1, const float* __restrict__ ae1,
                             const float* __restrict__ We2, const float* __restrict__ ae2,
                             const float* __restrict__ We3, const float* __restrict__ ae3) {
    int t = threadIdx.x;
    if (t < 4) {
        float s = 0.f;
        for (int c = 0; c < 64; c++) s += We1[t * 64 + c] * ae1[t * 64 + c];
        g_chv[t] = s;
    } else if (t < 8) {
        int h = t - 4;
        float s = 0.f;
        for (int c = 0; c < 64; c++) s += We2[h * 64 + c] * ae2[h * 64 + c];
        g_chv[4 + h] = s;
    } else if (t == 8) {
        float s = 0.f;
        for (int c = 0; c < 64; c++) s += We3[c] * ae3[c];
        g_chv[8] = s;
    }
}

#define EP_NONE 0
#define EP_GATE 1
#define EP_RELU 2

// ---------------- gemm5: bf16x3 m16n8k16, BM=128 BN=64 BK=32 (N=64 cases) --
#define SMEM_DB (15360 * 4)

template <int EP, bool SPLITOUT, bool WRITEC>
__global__ __launch_bounds__(256) void gemm5(
    const bf16* __restrict__ Agh, const bf16* __restrict__ Agl,
    const bf16* __restrict__ Bgh, const bf16* __restrict__ Bgl,
    const float* __restrict__ bias, const float* __restrict__ gateA,
    float* __restrict__ C, bf16* __restrict__ Ch, bf16* __restrict__ Cl,
    int M, int K, int N) {
    extern __shared__ uint32_t smu[];
    const int bm = blockIdx.y * 128, bn = blockIdx.x * 64;
    const int tid = threadIdx.x, lane = tid & 31, wid = tid >> 5;
    const int wm = wid >> 1, wn = wid & 1;
    const int lg = lane >> 2, lt = lane & 3;
    const int arow = tid >> 2, q = tid & 3;

    float acc[2][4][4];
#pragma unroll
    for (int mt = 0; mt < 2; mt++)
#pragma unroll
        for (int nt = 0; nt < 4; nt++)
#pragma unroll
            for (int j = 0; j < 4; j++) acc[mt][nt][j] = 0.f;

    uint4 rA[2][2], rB[2];
    const uint4 z16 = make_uint4(0u, 0u, 0u, 0u);

#pragma unroll
    for (int t = 0; t < 2; t++) {
        int grow = bm + arow + t * 64;
        if (grow < M) {
            rA[t][0] = ((const uint4*)(Agh + (size_t)grow * K))[q];
            rA[t][1] = ((const uint4*)(Agl + (size_t)grow * K))[q];
        } else { rA[t][0] = z16; rA[t][1] = z16; }
    }
    rB[0] = ((const uint4*)(Bgh + (size_t)(bn + arow) * K))[q];
    rB[1] = ((const uint4*)(Bgl + (size_t)(bn + arow) * K))[q];

    int p = 0;
    {
#pragma unroll
        for (int t = 0; t < 2; t++) {
            int row = arow + t * 64;
#pragma unroll
            for (int s = 0; s < 2; s++) {
                uint32_t* d = smu + s * 2560 + row * 20 + q * 4;
                uint4 v = rA[t][s];
                d[0] = v.x; d[1] = v.y; d[2] = v.z; d[3] = v.w;
            }
        }
#pragma unroll
        for (int s = 0; s < 2; s++) {
            uint32_t* d = smu + 10240 + s * 1280 + arow * 20 + q * 4;
            uint4 v = rB[s];
            d[0] = v.x; d[1] = v.y; d[2] = v.z; d[3] = v.w;
        }
    }
    __syncthreads();

    for (int k0 = 0; k0 < K; k0 += 32) {
        const bool more = (k0 + 32 < K);
        if (more) {
            int kn = k0 + 32;
#pragma unroll
            for (int t = 0; t < 2; t++) {
                int grow = bm + arow + t * 64;
                if (grow < M) {
                    rA[t][0] = ((const uint4*)(Agh + (size_t)grow * K + kn))[q];
                    rA[t][1] = ((const uint4*)(Agl + (size_t)grow * K + kn))[q];
                } else { rA[t][0] = z16; rA[t][1] = z16; }
            }
            rB[0] = ((const uint4*)(Bgh + (size_t)(bn + arow) * K + kn))[q];
            rB[1] = ((const uint4*)(Bgl + (size_t)(bn + arow) * K + kn))[q];
        }
        {
            const uint32_t* Ah = smu + (p * 2 + 0) * 2560;
            const uint32_t* Al = smu + (p * 2 + 1) * 2560;
            const uint32_t* Bh = smu + 10240 + (p * 2 + 0) * 1280;
            const uint32_t* Bl = smu + 10240 + (p * 2 + 1) * 1280;
#pragma unroll
            for (int ks = 0; ks < 2; ks++) {
                const int kp = ks * 8 + lt;
                uint32_t ah[2][4], al[2][4];
#pragma unroll
                for (int mt = 0; mt < 2; mt++) {
                    int r = wm * 32 + mt * 16 + lg;
                    ah[mt][0] = Ah[r * 20 + kp];
                    ah[mt][1] = Ah[(r + 8) * 20 + kp];
                    ah[mt][2] = Ah[r * 20 + kp + 4];
                    ah[mt][3] = Ah[(r + 8) * 20 + kp + 4];
                    al[mt][0] = Al[r * 20 + kp];
                    al[mt][1] = Al[(r + 8) * 20 + kp];
                    al[mt][2] = Al[r * 20 + kp + 4];
                    al[mt][3] = Al[(r + 8) * 20 + kp + 4];
                }
#pragma unroll
                for (int nt = 0; nt < 4; nt++) {
                    int c = wn * 32 + nt * 8 + lg;
                    uint32_t bh[2], bl2[2];
                    bh[0] = Bh[c * 20 + kp];
                    bh[1] = Bh[c * 20 + kp + 4];
                    bl2[0] = Bl[c * 20 + kp];
                    bl2[1] = Bl[c * 20 + kp + 4];
#pragma unroll
                    for (int mt = 0; mt < 2; mt++) {
                        mma_bf16(acc[mt][nt], ah[mt], bh);
                        mma_bf16(acc[mt][nt], al[mt], bh);
                        mma_bf16(acc[mt][nt], ah[mt], bl2);
                    }
                }
            }
        }
        if (more) {
            int pb = p ^ 1;
#pragma unroll
            for (int t = 0; t < 2; t++) {
                int row = arow + t * 64;
#pragma unroll
                for (int s = 0; s < 2; s++) {
                    uint32_t* d = smu + (pb * 2 + s) * 2560 + row * 20 + q * 4;
                    uint4 v = rA[t][s];
                    d[0] = v.x; d[1] = v.y; d[2] = v.z; d[3] = v.w;
                }
            }
#pragma unroll
            for (int s = 0; s < 2; s++) {
                uint32_t* d = smu + 10240 + (pb * 2 + s) * 1280 + arow * 20 + q * 4;
                uint4 v = rB[s];
                d[0] = v.x; d[1] = v.y; d[2] = v.z; d[3] = v.w;
            }
            __syncthreads();
            p = pb;
        }
    }
#pragma unroll
    for (int mt = 0; mt < 2; mt++) {
        int r0 = bm + wm * 32 + mt * 16 + lg;
#pragma unroll
        for (int nt = 0; nt < 4; nt++) {
            int c0 = bn + wn * 32 + nt * 8 + lt * 2;
#pragma unroll
            for (int j = 0; j < 4; j++) {
                int row = r0 + (j >> 1) * 8;
                int col = c0 + (j & 1);
                if (row >= M) continue;
                float v = acc[mt][nt][j] + (bias ? bias[col] : 0.f);
                if (EP == EP_GATE) v = gateA[(size_t)row * K + col] * sigf(v);
                else if (EP == EP_RELU) v = fmaxf(v, 0.f);
                size_t idx = (size_t)row * N + col;
                if (WRITEC) C[idx] = v;
                if (SPLITOUT) {
                    bf16 h, l; bf_split(v, h, l);
                    Ch[idx] = h; Cl[idx] = l;
                }
            }
        }
    }
}

// ---------------- gemm6: BM=128 BN=128, 4 warps 64x64, cp.async + ldmatrix --
// HB16: res half (col<256) -> fp32 C[row*256+col]; h half -> bf16 Hb[row*256+col-256]
#define SMEM2 (20480 * 4)

template <int EP, bool SPLITOUT, bool WRITEC, bool HB16>
__global__ __launch_bounds__(128) void gemm6(
    const bf16* __restrict__ Agh, const bf16* __restrict__ Agl,
    const bf16* __restrict__ Bgh, const bf16* __restrict__ Bgl,
    const float* __restrict__ bias, const float* __restrict__ gateA,
    float* __restrict__ C, bf16* __restrict__ Ch, bf16* __restrict__ Cl,
    bf16* __restrict__ Hb,
    int M, int K, int N) {
    extern __shared__ uint32_t smu[];
    const int bm = blockIdx.y * 128, bn = blockIdx.x * 128;
    const int tid = threadIdx.x, lane = tid & 31, wid = tid >> 5;
    const int wm = wid >> 1, wn = wid & 1;
    const int lg = lane >> 2, lt = lane & 3;
    const uint32_t smb = (uint32_t)__cvta_generic_to_shared(smu);

    const int lane7 = lane & 7;
    const int aoff = (wm * 64 + lane7 + ((lane >> 3) & 1) * 8) * 20 + ((lane >> 4) & 1) * 4;
    const int boff = (wn * 64 + lane7 + ((lane >> 4) & 1) * 8) * 20 + ((lane >> 3) & 1) * 4;

    float acc[4][8][4];
#pragma unroll
    for (int mt = 0; mt < 4; mt++)
#pragma unroll
        for (int nt = 0; nt < 8; nt++)
#pragma unroll
            for (int j = 0; j < 4; j++) acc[mt][nt][j] = 0.f;

    auto issue = [&](int p, int k0) {
#pragma unroll
        for (int i = 0; i < 4; i++) {
            int idx = tid + i * 128;
            int row = idx >> 2, q = idx & 3;
            int grow = bm + row;
            int sz = (grow < M) ? 16 : 0;
            int cg = (grow < M) ? grow : (M - 1);
            cp16(smb + (((p * 2 + 0) * 2560 + row * 20 + q * 4) << 2),
                 Agh + (size_t)cg * K + k0 + q * 8, sz);
            cp16(smb + (((p * 2 + 1) * 2560 + row * 20 + q * 4) << 2),
                 Agl + (size_t)cg * K + k0 + q * 8, sz);
            cp16(smb + ((10240 + (p * 2 + 0) * 2560 + row * 20 + q * 4) << 2),
                 Bgh + (size_t)(bn + row) * K + k0 + q * 8, 16);
            cp16(smb + ((10240 + (p * 2 + 1) * 2560 + row * 20 + q * 4) << 2),
                 Bgl + (size_t)(bn + row) * K + k0 + q * 8, 16);
        }
        cp_commit();
    };

    issue(0, 0);
    int p = 0;
    for (int k0 = 0; k0 < K; k0 += 32) {
        const bool more = (k0 + 32 < K);
        if (more) issue(p ^ 1, k0 + 32);
        if (more) cp_wait<1>(); else cp_wait<0>();
        __syncthreads();
        {
            const uint32_t baseAh = smb + (((p * 2 + 0) * 2560 + aoff) << 2);
            const uint32_t baseAl = smb + (((p * 2 + 1) * 2560 + aoff) << 2);
            const uint32_t baseBh = smb + ((10240 + (p * 2 + 0) * 2560 + boff) << 2);
            const uint32_t baseBl = smb + ((10240 + (p * 2 + 1) * 2560 + boff) << 2);
#pragma unroll
            for (int ks = 0; ks < 2; ks++) {
                uint32_t ah[4][4], al[4][4];
#pragma unroll
                for (int mt = 0; mt < 4; mt++) {
                    ldsm_x4(ah[mt][0], ah[mt][1], ah[mt][2], ah[mt][3],
                            baseAh + ((mt * 320 + ks * 8) << 2));
                    ldsm_x4(al[mt][0], al[mt][1], al[mt][2], al[mt][3],
                            baseAl + ((mt * 320 + ks * 8) << 2));
                }
#pragma unroll
                for (int j = 0; j < 4; j++) {
                    uint32_t bh0[2], bh1[2], bl0[2], bl1[2];
                    ldsm_x4(bh0[0], bh0[1], bh1[0], bh1[1],
                            baseBh + ((j * 320 + ks * 8) << 2));
                    ldsm_x4(bl0[0], bl0[1], bl1[0], bl1[1],
                            baseBl + ((j * 320 + ks * 8) << 2));
#pragma unroll
                    for (int mt = 0; mt < 4; mt++) {
                        mma_bf16(acc[mt][2 * j + 0], ah[mt], bh0);
                        mma_bf16(acc[mt][2 * j + 0], al[mt], bh0);
                        mma_bf16(acc[mt][2 * j + 0], ah[mt], bl0);
                        mma_bf16(acc[mt][2 * j + 1], ah[mt], bh1);
                        mma_bf16(acc[mt][2 * j + 1], al[mt], bh1);
                        mma_bf16(acc[mt][2 * j + 1], ah[mt], bl1);
                    }
                }
            }
        }
        __syncthreads();
        p ^= 1;
    }
    // epilogue
#pragma unroll
    for (int mt = 0; mt < 4; mt++) {
        int r0 = bm + wm * 64 + mt * 16 + lg;
#pragma unroll
        for (int nt = 0; nt < 8; nt++) {
            int c0 = bn + wn * 64 + nt * 8 + lt * 2;
            if (HB16) {
#pragma unroll
                for (int half = 0; half < 2; half++) {
                    int row = r0 + half * 8;
                    if (row >= M) continue;
                    float v0 = acc[mt][nt][half * 2 + 0] + bias[c0];
                    float v1 = acc[mt][nt][half * 2 + 1] + bias[c0 + 1];
                    if (c0 < 256) {
                        C[(size_t)row * 256 + c0] = v0;
                        C[(size_t)row * 256 + c0 + 1] = v1;
                    } else {
                        __nv_bfloat162 pr;
                        pr.x = __float2bfloat16(v0);
                        pr.y = __float2bfloat16(v1);
                        *(__nv_bfloat162*)&Hb[(size_t)row * 256 + c0 - 256] = pr;
                    }
                }
            } else {
#pragma unroll
                for (int j = 0; j < 4; j++) {
                    int row = r0 + (j >> 1) * 8;
                    int col = c0 + (j & 1);
                    if (row >= M) continue;
                    float v = acc[mt][nt][j] + (bias ? bias[col] : 0.f);
                    if (EP == EP_GATE) v = gateA[(size_t)row * K + col] * sigf(v);
                    else if (EP == EP_RELU) v = fmaxf(v, 0.f);
                    size_t idx = (size_t)row * N + col;
                    if (WRITEC) C[idx] = v;
                    if (SPLITOUT) {
                        bf16 h, l; bf_split(v, h, l);
                        Ch[idx] = h; Cl[idx] = l;
                    }
                }
            }
        }
    }
}

// ---------------- CSR build ----------------
__global__ void zero_kernel() {
    int i = blockIdx.x * blockDim.x + threadIdx.x;
    if (i < NN) { g_deg[i] = 0; g_cursor[i] = 0; g_easum[i] = 0.f; }
    if (i == 0) g_total = 0;
}
__global__ void deg_kernel(const int* __restrict__ dst, const float* __restrict__ ea) {
    int e = blockIdx.x * blockDim.x + threadIdx.x;
    if (e < NE) {
        int d = dst[e];
        atomicAdd(&g_deg[d], 1);
        atomicAdd(&g_easum[d], ea[e]);
    }
}
__global__ void alloc_kernel() {
    __shared__ int s[1024];
    __shared__ int base;
    int tid = threadIdx.x;
    int i = blockIdx.x * 1024 + tid;
    int v = (i < NN) ? g_deg[i] : 0;
    s[tid] = v;
    __syncthreads();
    for (int off = 1; off < 1024; off <<= 1) {
        int t = (tid >= off) ? s[tid - off] : 0;
        __syncthreads();
        s[tid] += t;
        __syncthreads();
    }
    int incl = s[tid];
    if (tid == 1023) base = atomicAdd(&g_total, s[1023]);
    __syncthreads();
    if (i < NN) {
        g_rowstart[i] = base + incl - v;
        g_loop[i] = g_easum[i] / fmaxf((float)v, 1.f);
    }
}
// scatter src + ea directly into CSR order (contiguous downstream reads)
__global__ void csr_kernel(const int* __restrict__ dst, const int* __restrict__ src,
                           const float* __restrict__ ea) {
    int e = blockIdx.x * blockDim.x + threadIdx.x;
    if (e < NE) {
        int d = dst[e];
        int pos = atomicAdd(&g_cursor[d], 1);
        int idx = g_rowstart[d] + pos;
        g_csr_src[idx] = src[e];
        g_csr_ea[idx] = ea[e];
    }
}

// ---------------- attention coefficients ----------------
template <int H, typename T>
__global__ void attn_kernel(const T* __restrict__ hbuf, int stride,
                            const float* __restrict__ a_s, const float* __restrict__ a_d) {
    int w = (blockIdx.x * blockDim.x + threadIdx.x) >> 5;
    int lane = threadIdx.x & 31;
    if (w >= NN * H) return;
    int n = w / H, hh = w % H;
    const T* hr = hbuf + (size_t)n * stride + hh * 64;
    float as0 = a_s[hh * 64 + lane], as1 = a_s[hh * 64 + lane + 32];
    float ad0 = a_d[hh * 64 + lane], ad1 = a_d[hh * 64 + lane + 32];
    float h0 = (float)hr[lane], h1 = (float)hr[lane + 32];
    float vs = h0 * as0 + h1 * as1;
    float vd = h0 * ad0 + h1 * ad1;
#pragma unroll
    for (int off = 16; off > 0; off >>= 1) {
        vs += __shfl_down_sync(0xffffffffu, vs, off);
        vd += __shfl_down_sync(0xffffffffu, vd, off);
    }
    if (lane == 0) { g_asrc[w] = vs; g_adst[w] = vd; }
}

// ---------------- per-node softmax aggregation (single pass, no max) -------
template <int H, int C, bool SPLIT, bool WRITEO, typename GT>
__global__ void agg3(const GT* __restrict__ hbuf, int hstride,
                     const float* __restrict__ bias, int choff,
                     const float* __restrict__ resid, int rstride,
                     float* __restrict__ out, bf16* __restrict__ outh,
                     bf16* __restrict__ outl) {
    constexpr int OUT = H * C;
    constexpr int CH = 64;
    __shared__ float s_alpha[CH * H];
    __shared__ int s_sid[CH];
    __shared__ float s_red[2 * H];

    const int n = blockIdx.x;
    const int tid = threadIdx.x;
    const int deg = g_deg[n];
    const int rs = g_rowstart[n];
    const int T = deg + 1;
    const float loopv = g_loop[n];

    float adst[H], chh[H], zloc[H];
#pragma unroll
    for (int h = 0; h < H; h++) zloc[h] = 0.f;
    if (tid < CH) {
#pragma unroll
        for (int h = 0; h < H; h++) { adst[h] = g_adst[n * H + h]; chh[h] = g_chv[choff + h]; }
    }

    const int hh = tid / C;
    float acc = 0.f;
    for (int base = 0; base < T; base += CH) {
        int i = base + tid;
        if (tid < CH && i < T) {
            int sN; float eav;
            if (i < deg) { sN = g_csr_src[rs + i]; eav = g_csr_ea[rs + i]; }
            else { sN = n; eav = loopv; }
#pragma unroll
            for (int h = 0; h < H; h++) {
                float v = g_asrc[sN * H + h] + adst[h] + chh[h] * eav;
                v = (v >= 0.f) ? v : 0.2f * v;
                float ex = __expf(v);
                s_alpha[tid * H + h] = ex;
                zloc[h] += ex;
            }
            s_sid[tid] = sN;
        }
        __syncthreads();
        int lim = min(CH, T - base);
        for (int j = 0; j < lim; j++)
            acc += s_alpha[j * H + hh] * (float)hbuf[(size_t)s_sid[j] * hstride + tid];
        __syncthreads();
    }
    if (tid < CH) {
#pragma unroll
        for (int off = 16; off > 0; off >>= 1)
#pragma unroll
            for (int h = 0; h < H; h++)
                zloc[h] += __shfl_xor_sync(0xffffffffu, zloc[h], off);
        if ((tid & 31) == 0) {
#pragma unroll
            for (int h = 0; h < H; h++) s_red[(tid >> 5) * H + h] = zloc[h];
        }
    }
    __syncthreads();
    float z = s_red[hh] + s_red[H + hh];
    float v = acc / z + bias[tid];
    v = (v >= 0.f) ? v : 0.01f * v;
    v += resid[(size_t)n * rstride + tid];
    size_t idx = (size_t)n * OUT + tid;
    if (WRITEO) out[idx] = v;
    if (SPLIT) {
        bf16 h, l; bf_split(v, h, l);
        outh[idx] = h; outl[idx] = l;
    }
}

// ---------------- driver ----------------
extern "C" void kernel_launch(void* const* d_in, const int* in_sizes, int n_in,
                              void* d_out, int out_size) {
    const float* x     = (const float*)d_in[0];
    const int*   eidx  = (const int*)d_in[1];
    const float* ea    = (const float*)d_in[2];
    const float* fa_w  = (const float*)d_in[3];
    const float* fa_b  = (const float*)d_in[4];
    const float* W1    = (const float*)d_in[5];
    const float* We1   = (const float*)d_in[6];
    const float* as1   = (const float*)d_in[7];
    const float* ad1   = (const float*)d_in[8];
    const float* ae1   = (const float*)d_in[9];
    const float* b1    = (const float*)d_in[10];
    const float* W2    = (const float*)d_in[11];
    const float* We2   = (const float*)d_in[12];
    const float* as2   = (const float*)d_in[13];
    const float* ad2   = (const float*)d_in[14];
    const float* ae2   = (const float*)d_in[15];
    const float* b2    = (const float*)d_in[16];
    const float* W3    = (const float*)d_in[17];
    const float* We3   = (const float*)d_in[18];
    const float* as3   = (const float*)d_in[19];
    const float* ad3   = (const float*)d_in[20];
    const float* ae3   = (const float*)d_in[21];
    const float* b3    = (const float*)d_in[22];
    const float* r1_w  = (const float*)d_in[23];
    const float* r1_b  = (const float*)d_in[24];
    const float* r2_w  = (const float*)d_in[25];
    const float* r2_b  = (const float*)d_in[26];
    const float* ffn_w1 = (const float*)d_in[27];
    const float* ffn_b1 = (const float*)d_in[28];
    const float* ffn_w2 = (const float*)d_in[29];
    const float* ffn_b2 = (const float*)d_in[30];
    float* out = (float*)d_out;

    const int* src = eidx;
    const int* dst = eidx + NE;

    bf16 *xh, *xl, *gxh, *gxl, *hb, *z1h, *z1l, *z2h, *z2l, *t64h, *t64l;
    bf16 *wfah, *wfal, *wb1h, *wb1l, *wb2h, *wb2l, *w3h, *w3l, *wf1h, *wf1l, *wf2h, *wf2l;
    float *res, *zself, *h3, *bb1, *bb2;
    cudaGetSymbolAddress((void**)&xh, g_xh);   cudaGetSymbolAddress((void**)&xl, g_xl);
    cudaGetSymbolAddress((void**)&gxh, g_gxh); cudaGetSymbolAddress((void**)&gxl, g_gxl);
    cudaGetSymbolAddress((void**)&res, g_res);
    cudaGetSymbolAddress((void**)&hb, g_hb);
    cudaGetSymbolAddress((void**)&z1h, g_z1h); cudaGetSymbolAddress((void**)&z1l, g_z1l);
    cudaGetSymbolAddress((void**)&z2h, g_z2h); cudaGetSymbolAddress((void**)&z2l, g_z2l);
    cudaGetSymbolAddress((void**)&t64h, g_t64h); cudaGetSymbolAddress((void**)&t64l, g_t64l);
    cudaGetSymbolAddress((void**)&zself, g_zself);
    cudaGetSymbolAddress((void**)&h3, g_h3);
    cudaGetSymbolAddress((void**)&wfah, g_wfa_h); cudaGetSymbolAddress((void**)&wfal, g_wfa_l);
    cudaGetSymbolAddress((void**)&wb1h, g_wb1_h); cudaGetSymbolAddress((void**)&wb1l, g_wb1_l);
    cudaGetSymbolAddress((void**)&wb2h, g_wb2_h); cudaGetSymbolAddress((void**)&wb2l, g_wb2_l);
    cudaGetSymbolAddress((void**)&w3h, g_w3_h);   cudaGetSymbolAddress((void**)&w3l, g_w3_l);
    cudaGetSymbolAddress((void**)&wf1h, g_wf1_h); cudaGetSymbolAddress((void**)&wf1l, g_wf1_l);
    cudaGetSymbolAddress((void**)&wf2h, g_wf2_h); cudaGetSymbolAddress((void**)&wf2l, g_wf2_l);
    cudaGetSymbolAddress((void**)&bb1, g_bb1);
    cudaGetSymbolAddress((void**)&bb2, g_bb2);

    cudaFuncSetAttribute(gemm5<EP_RELU, true, false>,
                         cudaFuncAttributeMaxDynamicSharedMemorySize, SMEM_DB);
    cudaFuncSetAttribute(gemm5<EP_NONE, false, true>,
                         cudaFuncAttributeMaxDynamicSharedMemorySize, SMEM_DB);
    cudaFuncSetAttribute(gemm6<EP_GATE, true, false, false>,
                         cudaFuncAttributeMaxDynamicSharedMemorySize, SMEM2);
    cudaFuncSetAttribute(gemm6<EP_NONE, false, true, true>,
                         cudaFuncAttributeMaxDynamicSharedMemorySize, SMEM2);

    const int TB = 256;
    const int nbN = (NN + TB - 1) / TB;
    const int nbE = (NE + TB - 1) / TB;
    const int gy = (NN + 127) / 128;

    // launch 1: weight prep for gate + layer1
    packall_kernel<<<(82944 + 255) / 256, 256>>>(fa_w, r1_w, W1, r1_b, r2_b);
    // launch 2: split x
    split_bf_kernel<<<(NN * 128 + 255) / 256, 256>>>(x, xh, xl, NN * 128);
    // launch 3: gate gemm (N=128, gemm6)
    gemm6<EP_GATE, true, false, false><<<dim3(1, gy), 128, SMEM2>>>(
        xh, xl, wfah, wfal, fa_b, x, nullptr, gxh, gxl, nullptr, NN, 128, 128);
    // launch 4: layer-1 GEMM (N=512, gemm6 HB16)  <-- profiled launch
    gemm6<EP_NONE, false, true, true><<<dim3(4, gy), 128, SMEM2>>>(
        gxh, gxl, wb1h, wb1l, bb1, nullptr, res, nullptr, nullptr, hb, NN, 128, 512);

    // CSR build + head constants
    zero_kernel<<<nbN, TB>>>();
    deg_kernel<<<nbE, TB>>>(dst, ea);
    alloc_kernel<<<(NN + 1023) / 1024, 1024>>>();
    csr_kernel<<<nbE, TB>>>(dst, src, ea);
    ch123_kernel<<<1, 32>>>(We1, ae1, We2, ae2, We3, ae3);

    // remaining weight packs
    packfuseT_kernel<<<(512 * 256 + 255) / 256, 256>>>(r2_w, W2, wb2h, wb2l, 256, 256);
    packT_kernel<<<(64 * 256 + 255) / 256, 256>>>(W3, w3h, w3l, 256, 64);
    packT_kernel<<<(64 * 128 + 255) / 256, 256>>>(ffn_w1, wf1h, wf1l, 128, 64);
    packT_kernel<<<(64 * 64 + 255) / 256, 256>>>(ffn_w2, wf2h, wf2l, 64, 64);

    // ffn path (N=64 -> gemm5)
    gemm5<EP_RELU, true, false><<<dim3(1, gy), 256, SMEM_DB>>>(
        gxh, gxl, wf1h, wf1l, ffn_b1, nullptr, nullptr, t64h, t64l, NN, 128, 64);
    gemm5<EP_NONE, false, true><<<dim3(1, gy), 256, SMEM_DB>>>(
        t64h, t64l, wf2h, wf2l, ffn_b2, nullptr, zself, nullptr, nullptr, NN, 64, 64);

    // layer 1 attention + aggregation (bf16 h)
    attn_kernel<4, bf16><<<(NN * 4 * 32 + TB - 1) / TB, TB>>>(hb, 256, as1, ad1);
    agg3<4, 64, true, false, bf16><<<NN, 256>>>(hb, 256, b1, 0, res, 256,
                                                nullptr, z1h, z1l);

    // layer 2 (gemm6 HB16)
    gemm6<EP_NONE, false, true, true><<<dim3(4, gy), 128, SMEM2>>>(
        z1h, z1l, wb2h, wb2l, bb2, nullptr, res, nullptr, nullptr, hb, NN, 256, 512);
    attn_kernel<4, bf16><<<(NN * 4 * 32 + TB - 1) / TB, TB>>>(hb, 256, as2, ad2);
    agg3<4, 64, true, false, bf16><<<NN, 256>>>(hb, 256, b2, 4, res, 256,
                                                nullptr, z2h, z2l);

    // layer 3 (N=64 -> gemm5, fp32 path)
    gemm5<EP_NONE, false, true><<<dim3(1, gy), 256, SMEM_DB>>>(
        z2h, z2l, w3h, w3l, nullptr, nullptr, h3, nullptr, nullptr, NN, 256, 64);
    attn_kernel<1, float><<<(NN * 32 + TB - 1) / TB, TB>>>(h3, 64, as3, ad3);
    agg3<1, 64, false, true, float><<<NN, 64>>>(h3, 64, b3, 8, zself, 64,
                                                out, nullptr, nullptr);
}

// round 17
// speedup vs baseline: 1.1750x; 1.0585x over previous
#include <cuda_runtime.h>
#include <cuda_bf16.h>
#include <math.h>
#include <stdint.h>

#define NN 50000
#define NE 800000

typedef __nv_bfloat16 bf16;

// ---------------- scratch (device globals) ----------------
__device__ __align__(16) bf16 g_xh[NN * 128], g_xl[NN * 128];
__device__ __align__(16) bf16 g_gxh[NN * 128], g_gxl[NN * 128];
__device__ float g_res[NN * 256];                         // residual half (fp32)
__device__ __align__(16) bf16 g_hb[NN * 256];             // h half (bf16) for gather
__device__ __align__(16) bf16 g_z1h[NN * 256], g_z1l[NN * 256];
__device__ __align__(16) bf16 g_z2h[NN * 256], g_z2l[NN * 256];
__device__ __align__(16) bf16 g_t64h[NN * 64], g_t64l[NN * 64];
__device__ float g_zself[NN * 64];
__device__ float g_h3[NN * 64];
__device__ float g_asrc[NN * 4];
__device__ float g_adst[NN * 4];
__device__ float g_loop[NN];
__device__ float g_easum[NN];
__device__ int   g_deg[NN];
__device__ int   g_rowstart[NN];
__device__ int   g_cursor[NN];
__device__ int   g_csr_src[NE];
__device__ float g_csr_ea[NE];
__device__ float g_chv[12];     // [0..3] layer1, [4..7] layer2, [8] layer3
__device__ int   g_total;
// transposed [n][k] k-major bf16 weight splits
__device__ __align__(16) bf16 g_wfa_h[128 * 128], g_wfa_l[128 * 128];
__device__ __align__(16) bf16 g_wb1_h[512 * 128], g_wb1_l[512 * 128];
__device__ __align__(16) bf16 g_wb2_h[512 * 256], g_wb2_l[512 * 256];
__device__ __align__(16) bf16 g_w3_h[64 * 256],  g_w3_l[64 * 256];
__device__ __align__(16) bf16 g_wf1_h[64 * 128], g_wf1_l[64 * 128];
__device__ __align__(16) bf16 g_wf2_h[64 * 64],  g_wf2_l[64 * 64];
__device__ float g_bb1[512], g_bb2[512];

__device__ __forceinline__ float sigf(float x) { return 1.f / (1.f + __expf(-x)); }

__device__ __forceinline__ void bf_split(float x, bf16& h, bf16& l) {
    h = __float2bfloat16(x);
    l = __float2bfloat16(x - __bfloat162float(h));
}

__device__ __forceinline__ void mma_bf16(float* c, const uint32_t* a, const uint32_t* b) {
    asm volatile(
        "mma.sync.aligned.m16n8k16.row.col.f32.bf16.bf16.f32 "
        "{%0,%1,%2,%3}, {%4,%5,%6,%7}, {%8,%9}, {%0,%1,%2,%3};\n"
        : "+f"(c[0]), "+f"(c[1]), "+f"(c[2]), "+f"(c[3])
        : "r"(a[0]), "r"(a[1]), "r"(a[2]), "r"(a[3]), "r"(b[0]), "r"(b[1]));
}

__device__ __forceinline__ void ldsm_x4(uint32_t& r0, uint32_t& r1, uint32_t& r2,
                                        uint32_t& r3, uint32_t addr) {
    asm volatile("ldmatrix.sync.aligned.m8n8.x4.shared.b16 {%0,%1,%2,%3}, [%4];"
                 : "=r"(r0), "=r"(r1), "=r"(r2), "=r"(r3) : "r"(addr));
}

__device__ __forceinline__ void cp16(uint32_t dst, const void* src, int sz) {
    asm volatile("cp.async.cg.shared.global [%0], [%1], 16, %2;\n"
                 :: "r"(dst), "l"(src), "r"(sz));
}
__device__ __forceinline__ void cp_commit() {
    asm volatile("cp.async.commit_group;\n");
}
template <int N>
__device__ __forceinline__ void cp_wait() {
    asm volatile("cp.async.wait_group %0;\n" :: "n"(N));
}

// ---------------- pack / split kernels ----------------
__global__ void split_bf_kernel(const float* __restrict__ s, bf16* __restrict__ dh,
                                bf16* __restrict__ dl, int n) {
    int i = blockIdx.x * blockDim.x + threadIdx.x;
    if (i < n) { bf16 h, l; bf_split(s[i], h, l); dh[i] = h; dl[i] = l; }
}
__global__ void packall_kernel(const float* __restrict__ fa_w,
                               const float* __restrict__ r1_w, const float* __restrict__ W1,
                               const float* __restrict__ r1_b, const float* __restrict__ r2_b) {
    int i = blockIdx.x * blockDim.x + threadIdx.x;
    if (i < 16384) {
        int n = i >> 7, k = i & 127;
        bf16 h, l; bf_split(fa_w[k * 128 + n], h, l);
        g_wfa_h[i] = h; g_wfa_l[i] = l;
    } else if (i < 16384 + 65536) {
        int j = i - 16384;
        int n = j >> 7, k = j & 127;
        float v = (n < 256) ? r1_w[k * 256 + n] : W1[k * 256 + n - 256];
        bf16 h, l; bf_split(v, h, l);
        g_wb1_h[j] = h; g_wb1_l[j] = l;
    } else if (i < 16384 + 65536 + 512) {
        int j = i - 81920;
        g_bb1[j] = (j < 256) ? r1_b[j] : 0.f;
    } else if (i < 16384 + 65536 + 1024) {
        int j = i - 82432;
        g_bb2[j] = (j < 256) ? r2_b[j] : 0.f;
    }
}
__global__ void packT_kernel(const float* __restrict__ W, bf16* __restrict__ th,
                             bf16* __restrict__ tl, int K_, int N_) {
    int i = blockIdx.x * blockDim.x + threadIdx.x;
    if (i < K_ * N_) {
        int n = i / K_, k = i % K_;
        bf16 h, l; bf_split(W[k * N_ + n], h, l);
        th[i] = h; tl[i] = l;
    }
}
__global__ void packfuseT_kernel(const float* __restrict__ A_, const float* __restrict__ B_,
                                 bf16* __restrict__ th, bf16* __restrict__ tl,
                                 int K_, int half) {
    int i = blockIdx.x * blockDim.x + threadIdx.x;
    if (i < 2 * half * K_) {
        int n = i / K_, k = i % K_;
        float v = (n < half) ? A_[k * half + n] : B_[k * half + n - half];
        bf16 h, l; bf_split(v, h, l);
        th[i] = h; tl[i] = l;
    }
}
__global__ void ch123_kernel(const float* __restrict__ We1, const float* __restrict__ ae1,
                             const float* __restrict__ We2, const float* __restrict__ ae2,
                             const float* __restrict__ We3, const float* __restrict__ ae3) {
    int t = threadIdx.x;
    if (t < 4) {
        float s = 0.f;
        for (int c = 0; c < 64; c++) s += We1[t * 64 + c] * ae1[t * 64 + c];
        g_chv[t] = s;
    } else if (t < 8) {
        int h = t - 4;
        float s = 0.f;
        for (int c = 0; c < 64; c++) s += We2[h * 64 + c] * ae2[h * 64 + c];
        g_chv[4 + h] = s;
    } else if (t == 8) {
        float s = 0.f;
        for (int c = 0; c < 64; c++) s += We3[c] * ae3[c];
        g_chv[8] = s;
    }
}

#define EP_NONE 0
#define EP_GATE 1
#define EP_RELU 2

// ---------------- gemm5: bf16x3 m16n8k16, BM=128 BN=64 BK=32 (N=64 cases) --
#define SMEM_DB (15360 * 4)

template <int EP, bool SPLITOUT, bool WRITEC>
__global__ __launch_bounds__(256) void gemm5(
    const bf16* __restrict__ Agh, const bf16* __restrict__ Agl,
    const bf16* __restrict__ Bgh, const bf16* __restrict__ Bgl,
    const float* __restrict__ bias, const float* __restrict__ gateA,
    float* __restrict__ C, bf16* __restrict__ Ch, bf16* __restrict__ Cl,
    int M, int K, int N) {
    extern __shared__ uint32_t smu[];
    const int bm = blockIdx.y * 128, bn = blockIdx.x * 64;
    const int tid = threadIdx.x, lane = tid & 31, wid = tid >> 5;
    const int wm = wid >> 1, wn = wid & 1;
    const int lg = lane >> 2, lt = lane & 3;
    const int arow = tid >> 2, q = tid & 3;

    float acc[2][4][4];
#pragma unroll
    for (int mt = 0; mt < 2; mt++)
#pragma unroll
        for (int nt = 0; nt < 4; nt++)
#pragma unroll
            for (int j = 0; j < 4; j++) acc[mt][nt][j] = 0.f;

    uint4 rA[2][2], rB[2];
    const uint4 z16 = make_uint4(0u, 0u, 0u, 0u);

#pragma unroll
    for (int t = 0; t < 2; t++) {
        int grow = bm + arow + t * 64;
        if (grow < M) {
            rA[t][0] = ((const uint4*)(Agh + (size_t)grow * K))[q];
            rA[t][1] = ((const uint4*)(Agl + (size_t)grow * K))[q];
        } else { rA[t][0] = z16; rA[t][1] = z16; }
    }
    rB[0] = ((const uint4*)(Bgh + (size_t)(bn + arow) * K))[q];
    rB[1] = ((const uint4*)(Bgl + (size_t)(bn + arow) * K))[q];

    int p = 0;
    {
#pragma unroll
        for (int t = 0; t < 2; t++) {
            int row = arow + t * 64;
#pragma unroll
            for (int s = 0; s < 2; s++) {
                uint32_t* d = smu + s * 2560 + row * 20 + q * 4;
                uint4 v = rA[t][s];
                d[0] = v.x; d[1] = v.y; d[2] = v.z; d[3] = v.w;
            }
        }
#pragma unroll
        for (int s = 0; s < 2; s++) {
            uint32_t* d = smu + 10240 + s * 1280 + arow * 20 + q * 4;
            uint4 v = rB[s];
            d[0] = v.x; d[1] = v.y; d[2] = v.z; d[3] = v.w;
        }
    }
    __syncthreads();

    for (int k0 = 0; k0 < K; k0 += 32) {
        const bool more = (k0 + 32 < K);
        if (more) {
            int kn = k0 + 32;
#pragma unroll
            for (int t = 0; t < 2; t++) {
                int grow = bm + arow + t * 64;
                if (grow < M) {
                    rA[t][0] = ((const uint4*)(Agh + (size_t)grow * K + kn))[q];
                    rA[t][1] = ((const uint4*)(Agl + (size_t)grow * K + kn))[q];
                } else { rA[t][0] = z16; rA[t][1] = z16; }
            }
            rB[0] = ((const uint4*)(Bgh + (size_t)(bn + arow) * K + kn))[q];
            rB[1] = ((const uint4*)(Bgl + (size_t)(bn + arow) * K + kn))[q];
        }
        {
            const uint32_t* Ah = smu + (p * 2 + 0) * 2560;
            const uint32_t* Al = smu + (p * 2 + 1) * 2560;
            const uint32_t* Bh = smu + 10240 + (p * 2 + 0) * 1280;
            const uint32_t* Bl = smu + 10240 + (p * 2 + 1) * 1280;
#pragma unroll
            for (int ks = 0; ks < 2; ks++) {
                const int kp = ks * 8 + lt;
                uint32_t ah[2][4], al[2][4];
#pragma unroll
                for (int mt = 0; mt < 2; mt++) {
                    int r = wm * 32 + mt * 16 + lg;
                    ah[mt][0] = Ah[r * 20 + kp];
                    ah[mt][1] = Ah[(r + 8) * 20 + kp];
                    ah[mt][2] = Ah[r * 20 + kp + 4];
                    ah[mt][3] = Ah[(r + 8) * 20 + kp + 4];
                    al[mt][0] = Al[r * 20 + kp];
                    al[mt][1] = Al[(r + 8) * 20 + kp];
                    al[mt][2] = Al[r * 20 + kp + 4];
                    al[mt][3] = Al[(r + 8) * 20 + kp + 4];
                }
#pragma unroll
                for (int nt = 0; nt < 4; nt++) {
                    int c = wn * 32 + nt * 8 + lg;
                    uint32_t bh[2], bl2[2];
                    bh[0] = Bh[c * 20 + kp];
                    bh[1] = Bh[c * 20 + kp + 4];
                    bl2[0] = Bl[c * 20 + kp];
                    bl2[1] = Bl[c * 20 + kp + 4];
#pragma unroll
                    for (int mt = 0; mt < 2; mt++) {
                        mma_bf16(acc[mt][nt], ah[mt], bh);
                        mma_bf16(acc[mt][nt], al[mt], bh);
                        mma_bf16(acc[mt][nt], ah[mt], bl2);
                    }
                }
            }
        }
        if (more) {
            int pb = p ^ 1;
#pragma unroll
            for (int t = 0; t < 2; t++) {
                int row = arow + t * 64;
#pragma unroll
                for (int s = 0; s < 2; s++) {
                    uint32_t* d = smu + (pb * 2 + s) * 2560 + row * 20 + q * 4;
                    uint4 v = rA[t][s];
                    d[0] = v.x; d[1] = v.y; d[2] = v.z; d[3] = v.w;
                }
            }
#pragma unroll
            for (int s = 0; s < 2; s++) {
                uint32_t* d = smu + 10240 + (pb * 2 + s) * 1280 + arow * 20 + q * 4;
                uint4 v = rB[s];
                d[0] = v.x; d[1] = v.y; d[2] = v.z; d[3] = v.w;
            }
            __syncthreads();
            p = pb;
        }
    }
#pragma unroll
    for (int mt = 0; mt < 2; mt++) {
        int r0 = bm + wm * 32 + mt * 16 + lg;
#pragma unroll
        for (int nt = 0; nt < 4; nt++) {
            int c0 = bn + wn * 32 + nt * 8 + lt * 2;
#pragma unroll
            for (int j = 0; j < 4; j++) {
                int row = r0 + (j >> 1) * 8;
                int col = c0 + (j & 1);
                if (row >= M) continue;
                float v = acc[mt][nt][j] + (bias ? bias[col] : 0.f);
                if (EP == EP_GATE) v = gateA[(size_t)row * K + col] * sigf(v);
                else if (EP == EP_RELU) v = fmaxf(v, 0.f);
                size_t idx = (size_t)row * N + col;
                if (WRITEC) C[idx] = v;
                if (SPLITOUT) {
                    bf16 h, l; bf_split(v, h, l);
                    Ch[idx] = h; Cl[idx] = l;
                }
            }
        }
    }
}

// ---------------- gemm6: BM=128 BN=128, 4 warps 64x64, cp.async + ldmatrix --
// HB16: res half (col<256) -> fp32 C[row*256+col]; h half -> bf16 Hb[row*256+col-256]
#define SMEM2 (20480 * 4)

template <int EP, bool SPLITOUT, bool WRITEC, bool HB16>
__global__ __launch_bounds__(128) void gemm6(
    const bf16* __restrict__ Agh, const bf16* __restrict__ Agl,
    const bf16* __restrict__ Bgh, const bf16* __restrict__ Bgl,
    const float* __restrict__ bias, const float* __restrict__ gateA,
    float* __restrict__ C, bf16* __restrict__ Ch, bf16* __restrict__ Cl,
    bf16* __restrict__ Hb,
    int M, int K, int N) {
    extern __shared__ uint32_t smu[];
    const int bm = blockIdx.y * 128, bn = blockIdx.x * 128;
    const int tid = threadIdx.x, lane = tid & 31, wid = tid >> 5;
    const int wm = wid >> 1, wn = wid & 1;
    const int lg = lane >> 2, lt = lane & 3;
    const uint32_t smb = (uint32_t)__cvta_generic_to_shared(smu);

    const int lane7 = lane & 7;
    const int aoff = (wm * 64 + lane7 + ((lane >> 3) & 1) * 8) * 20 + ((lane >> 4) & 1) * 4;
    const int boff = (wn * 64 + lane7 + ((lane >> 4) & 1) * 8) * 20 + ((lane >> 3) & 1) * 4;

    float acc[4][8][4];
#pragma unroll
    for (int mt = 0; mt < 4; mt++)
#pragma unroll
        for (int nt = 0; nt < 8; nt++)
#pragma unroll
            for (int j = 0; j < 4; j++) acc[mt][nt][j] = 0.f;

    auto issue = [&](int p, int k0) {
#pragma unroll
        for (int i = 0; i < 4; i++) {
            int idx = tid + i * 128;
            int row = idx >> 2, q = idx & 3;
            int grow = bm + row;
            int sz = (grow < M) ? 16 : 0;
            int cg = (grow < M) ? grow : (M - 1);
            cp16(smb + (((p * 2 + 0) * 2560 + row * 20 + q * 4) << 2),
                 Agh + (size_t)cg * K + k0 + q * 8, sz);
            cp16(smb + (((p * 2 + 1) * 2560 + row * 20 + q * 4) << 2),
                 Agl + (size_t)cg * K + k0 + q * 8, sz);
            cp16(smb + ((10240 + (p * 2 + 0) * 2560 + row * 20 + q * 4) << 2),
                 Bgh + (size_t)(bn + row) * K + k0 + q * 8, 16);
            cp16(smb + ((10240 + (p * 2 + 1) * 2560 + row * 20 + q * 4) << 2),
                 Bgl + (size_t)(bn + row) * K + k0 + q * 8, 16);
        }
        cp_commit();
    };

    issue(0, 0);
    int p = 0;
    for (int k0 = 0; k0 < K; k0 += 32) {
        const bool more = (k0 + 32 < K);
        if (more) issue(p ^ 1, k0 + 32);
        if (more) cp_wait<1>(); else cp_wait<0>();
        __syncthreads();
        {
            const uint32_t baseAh = smb + (((p * 2 + 0) * 2560 + aoff) << 2);
            const uint32_t baseAl = smb + (((p * 2 + 1) * 2560 + aoff) << 2);
            const uint32_t baseBh = smb + ((10240 + (p * 2 + 0) * 2560 + boff) << 2);
            const uint32_t baseBl = smb + ((10240 + (p * 2 + 1) * 2560 + boff) << 2);
#pragma unroll
            for (int ks = 0; ks < 2; ks++) {
                uint32_t ah[4][4], al[4][4];
#pragma unroll
                for (int mt = 0; mt < 4; mt++) {
                    ldsm_x4(ah[mt][0], ah[mt][1], ah[mt][2], ah[mt][3],
                            baseAh + ((mt * 320 + ks * 8) << 2));
                    ldsm_x4(al[mt][0], al[mt][1], al[mt][2], al[mt][3],
                            baseAl + ((mt * 320 + ks * 8) << 2));
                }
#pragma unroll
                for (int j = 0; j < 4; j++) {
                    uint32_t bh0[2], bh1[2], bl0[2], bl1[2];
                    ldsm_x4(bh0[0], bh0[1], bh1[0], bh1[1],
                            baseBh + ((j * 320 + ks * 8) << 2));
                    ldsm_x4(bl0[0], bl0[1], bl1[0], bl1[1],
                            baseBl + ((j * 320 + ks * 8) << 2));
#pragma unroll
                    for (int mt = 0; mt < 4; mt++) {
                        mma_bf16(acc[mt][2 * j + 0], ah[mt], bh0);
                        mma_bf16(acc[mt][2 * j + 0], al[mt], bh0);
                        mma_bf16(acc[mt][2 * j + 0], ah[mt], bl0);
                        mma_bf16(acc[mt][2 * j + 1], ah[mt], bh1);
                        mma_bf16(acc[mt][2 * j + 1], al[mt], bh1);
                        mma_bf16(acc[mt][2 * j + 1], ah[mt], bl1);
                    }
                }
            }
        }
        __syncthreads();
        p ^= 1;
    }
    // epilogue
#pragma unroll
    for (int mt = 0; mt < 4; mt++) {
        int r0 = bm + wm * 64 + mt * 16 + lg;
#pragma unroll
        for (int nt = 0; nt < 8; nt++) {
            int c0 = bn + wn * 64 + nt * 8 + lt * 2;
            if (HB16) {
#pragma unroll
                for (int half = 0; half < 2; half++) {
                    int row = r0 + half * 8;
                    if (row >= M) continue;
                    float v0 = acc[mt][nt][half * 2 + 0] + bias[c0];
                    float v1 = acc[mt][nt][half * 2 + 1] + bias[c0 + 1];
                    if (c0 < 256) {
                        C[(size_t)row * 256 + c0] = v0;
                        C[(size_t)row * 256 + c0 + 1] = v1;
                    } else {
                        __nv_bfloat162 pr;
                        pr.x = __float2bfloat16(v0);
                        pr.y = __float2bfloat16(v1);
                        *(__nv_bfloat162*)&Hb[(size_t)row * 256 + c0 - 256] = pr;
                    }
                }
            } else {
#pragma unroll
                for (int j = 0; j < 4; j++) {
                    int row = r0 + (j >> 1) * 8;
                    int col = c0 + (j & 1);
                    if (row >= M) continue;
                    float v = acc[mt][nt][j] + (bias ? bias[col] : 0.f);
                    if (EP == EP_GATE) v = gateA[(size_t)row * K + col] * sigf(v);
                    else if (EP == EP_RELU) v = fmaxf(v, 0.f);
                    size_t idx = (size_t)row * N + col;
                    if (WRITEC) C[idx] = v;
                    if (SPLITOUT) {
                        bf16 h, l; bf_split(v, h, l);
                        Ch[idx] = h; Cl[idx] = l;
                    }
                }
            }
        }
    }
}

// ---------------- CSR build ----------------
__global__ void zero_kernel() {
    int i = blockIdx.x * blockDim.x + threadIdx.x;
    if (i < NN) { g_deg[i] = 0; g_cursor[i] = 0; g_easum[i] = 0.f; }
    if (i == 0) g_total = 0;
}
__global__ void deg_kernel(const int* __restrict__ dst, const float* __restrict__ ea) {
    int e = blockIdx.x * blockDim.x + threadIdx.x;
    if (e < NE) {
        int d = dst[e];
        atomicAdd(&g_deg[d], 1);
        atomicAdd(&g_easum[d], ea[e]);
    }
}
__global__ void alloc_kernel() {
    __shared__ int s[1024];
    __shared__ int base;
    int tid = threadIdx.x;
    int i = blockIdx.x * 1024 + tid;
    int v = (i < NN) ? g_deg[i] : 0;
    s[tid] = v;
    __syncthreads();
    for (int off = 1; off < 1024; off <<= 1) {
        int t = (tid >= off) ? s[tid - off] : 0;
        __syncthreads();
        s[tid] += t;
        __syncthreads();
    }
    int incl = s[tid];
    if (tid == 1023) base = atomicAdd(&g_total, s[1023]);
    __syncthreads();
    if (i < NN) {
        g_rowstart[i] = base + incl - v;
        g_loop[i] = g_easum[i] / fmaxf((float)v, 1.f);
    }
}
// scatter src + ea directly into CSR order (contiguous downstream reads)
__global__ void csr_kernel(const int* __restrict__ dst, const int* __restrict__ src,
                           const float* __restrict__ ea) {
    int e = blockIdx.x * blockDim.x + threadIdx.x;
    if (e < NE) {
        int d = dst[e];
        int pos = atomicAdd(&g_cursor[d], 1);
        int idx = g_rowstart[d] + pos;
        g_csr_src[idx] = src[e];
        g_csr_ea[idx] = ea[e];
    }
}

// ---------------- attention coefficients ----------------
template <int H, typename T>
__global__ void attn_kernel(const T* __restrict__ hbuf, int stride,
                            const float* __restrict__ a_s, const float* __restrict__ a_d) {
    int w = (blockIdx.x * blockDim.x + threadIdx.x) >> 5;
    int lane = threadIdx.x & 31;
    if (w >= NN * H) return;
    int n = w / H, hh = w % H;
    const T* hr = hbuf + (size_t)n * stride + hh * 64;
    float as0 = a_s[hh * 64 + lane], as1 = a_s[hh * 64 + lane + 32];
    float ad0 = a_d[hh * 64 + lane], ad1 = a_d[hh * 64 + lane + 32];
    float h0 = (float)hr[lane], h1 = (float)hr[lane + 32];
    float vs = h0 * as0 + h1 * as1;
    float vd = h0 * ad0 + h1 * ad1;
#pragma unroll
    for (int off = 16; off > 0; off >>= 1) {
        vs += __shfl_down_sync(0xffffffffu, vs, off);
        vd += __shfl_down_sync(0xffffffffu, vd, off);
    }
    if (lane == 0) { g_asrc[w] = vs; g_adst[w] = vd; }
}

// ---------------- per-node softmax aggregation ----------------
// single pass; z accumulated for free during the gather (smem broadcast reads)
template <int H, int C, bool SPLIT, bool WRITEO, typename GT>
__global__ void agg4(const GT* __restrict__ hbuf, int hstride,
                     const float* __restrict__ bias, int choff,
                     const float* __restrict__ resid, int rstride,
                     float* __restrict__ out, bf16* __restrict__ outh,
                     bf16* __restrict__ outl) {
    constexpr int OUT = H * C;
    constexpr int CH = 64;   // entries staged per chunk (OUT == CH * H)
    __shared__ float s_alpha[CH * H];
    __shared__ int s_sid[CH];

    const int n = blockIdx.x;
    const int tid = threadIdx.x;
    const int deg = g_deg[n];
    const int rs = g_rowstart[n];
    const int T = deg + 1;
    const float loopv = g_loop[n];

    // staging role: entry je, head he (all OUT threads participate)
    const int je = tid / H;
    const int he = tid % H;
    const float adsth = g_adst[n * H + he];
    const float chhh = g_chv[choff + he];

    const int hh = tid / C;
    float acc = 0.f, zacc = 0.f;
    for (int base = 0; base < T; base += CH) {
        int i = base + je;
        if (i < T) {
            int sN; float eav;
            if (i < deg) { sN = g_csr_src[rs + i]; eav = g_csr_ea[rs + i]; }
            else { sN = n; eav = loopv; }
            float v = g_asrc[sN * H + he] + adsth + chhh * eav;
            v = (v >= 0.f) ? v : 0.2f * v;
            s_alpha[je * H + he] = __expf(v);
            if (he == 0) s_sid[je] = sN;
        }
        __syncthreads();
        int lim = min(CH, T - base);
        for (int j = 0; j < lim; j++) {
            float a = s_alpha[j * H + hh];
            zacc += a;
            acc += a * (float)hbuf[(size_t)s_sid[j] * hstride + tid];
        }
        __syncthreads();
    }
    float v = acc / zacc + bias[tid];
    v = (v >= 0.f) ? v : 0.01f * v;
    v += resid[(size_t)n * rstride + tid];
    size_t idx = (size_t)n * OUT + tid;
    if (WRITEO) out[idx] = v;
    if (SPLIT) {
        bf16 h, l; bf_split(v, h, l);
        outh[idx] = h; outl[idx] = l;
    }
}

// ---------------- driver ----------------
extern "C" void kernel_launch(void* const* d_in, const int* in_sizes, int n_in,
                              void* d_out, int out_size) {
    const float* x     = (const float*)d_in[0];
    const int*   eidx  = (const int*)d_in[1];
    const float* ea    = (const float*)d_in[2];
    const float* fa_w  = (const float*)d_in[3];
    const float* fa_b  = (const float*)d_in[4];
    const float* W1    = (const float*)d_in[5];
    const float* We1   = (const float*)d_in[6];
    const float* as1   = (const float*)d_in[7];
    const float* ad1   = (const float*)d_in[8];
    const float* ae1   = (const float*)d_in[9];
    const float* b1    = (const float*)d_in[10];
    const float* W2    = (const float*)d_in[11];
    const float* We2   = (const float*)d_in[12];
    const float* as2   = (const float*)d_in[13];
    const float* ad2   = (const float*)d_in[14];
    const float* ae2   = (const float*)d_in[15];
    const float* b2    = (const float*)d_in[16];
    const float* W3    = (const float*)d_in[17];
    const float* We3   = (const float*)d_in[18];
    const float* as3   = (const float*)d_in[19];
    const float* ad3   = (const float*)d_in[20];
    const float* ae3   = (const float*)d_in[21];
    const float* b3    = (const float*)d_in[22];
    const float* r1_w  = (const float*)d_in[23];
    const float* r1_b  = (const float*)d_in[24];
    const float* r2_w  = (const float*)d_in[25];
    const float* r2_b  = (const float*)d_in[26];
    const float* ffn_w1 = (const float*)d_in[27];
    const float* ffn_b1 = (const float*)d_in[28];
    const float* ffn_w2 = (const float*)d_in[29];
    const float* ffn_b2 = (const float*)d_in[30];
    float* out = (float*)d_out;

    const int* src = eidx;
    const int* dst = eidx + NE;

    bf16 *xh, *xl, *gxh, *gxl, *hb, *z1h, *z1l, *z2h, *z2l, *t64h, *t64l;
    bf16 *wfah, *wfal, *wb1h, *wb1l, *wb2h, *wb2l, *w3h, *w3l, *wf1h, *wf1l, *wf2h, *wf2l;
    float *res, *zself, *h3, *bb1, *bb2;
    cudaGetSymbolAddress((void**)&xh, g_xh);   cudaGetSymbolAddress((void**)&xl, g_xl);
    cudaGetSymbolAddress((void**)&gxh, g_gxh); cudaGetSymbolAddress((void**)&gxl, g_gxl);
    cudaGetSymbolAddress((void**)&res, g_res);
    cudaGetSymbolAddress((void**)&hb, g_hb);
    cudaGetSymbolAddress((void**)&z1h, g_z1h); cudaGetSymbolAddress((void**)&z1l, g_z1l);
    cudaGetSymbolAddress((void**)&z2h, g_z2h); cudaGetSymbolAddress((void**)&z2l, g_z2l);
    cudaGetSymbolAddress((void**)&t64h, g_t64h); cudaGetSymbolAddress((void**)&t64l, g_t64l);
    cudaGetSymbolAddress((void**)&zself, g_zself);
    cudaGetSymbolAddress((void**)&h3, g_h3);
    cudaGetSymbolAddress((void**)&wfah, g_wfa_h); cudaGetSymbolAddress((void**)&wfal, g_wfa_l);
    cudaGetSymbolAddress((void**)&wb1h, g_wb1_h); cudaGetSymbolAddress((void**)&wb1l, g_wb1_l);
    cudaGetSymbolAddress((void**)&wb2h, g_wb2_h); cudaGetSymbolAddress((void**)&wb2l, g_wb2_l);
    cudaGetSymbolAddress((void**)&w3h, g_w3_h);   cudaGetSymbolAddress((void**)&w3l, g_w3_l);
    cudaGetSymbolAddress((void**)&wf1h, g_wf1_h); cudaGetSymbolAddress((void**)&wf1l, g_wf1_l);
    cudaGetSymbolAddress((void**)&wf2h, g_wf2_h); cudaGetSymbolAddress((void**)&wf2l, g_wf2_l);
    cudaGetSymbolAddress((void**)&bb1, g_bb1);
    cudaGetSymbolAddress((void**)&bb2, g_bb2);

    cudaFuncSetAttribute(gemm5<EP_RELU, true, false>,
                         cudaFuncAttributeMaxDynamicSharedMemorySize, SMEM_DB);
    cudaFuncSetAttribute(gemm5<EP_NONE, false, true>,
                         cudaFuncAttributeMaxDynamicSharedMemorySize, SMEM_DB);
    cudaFuncSetAttribute(gemm6<EP_GATE, true, false, false>,
                         cudaFuncAttributeMaxDynamicSharedMemorySize, SMEM2);
    cudaFuncSetAttribute(gemm6<EP_NONE, false, true, true>,
                         cudaFuncAttributeMaxDynamicSharedMemorySize, SMEM2);

    const int TB = 256;
    const int nbN = (NN + TB - 1) / TB;
    const int nbE = (NE + TB - 1) / TB;
    const int gy = (NN + 127) / 128;

    // launch 1: weight prep for gate + layer1
    packall_kernel<<<(82944 + 255) / 256, 256>>>(fa_w, r1_w, W1, r1_b, r2_b);
    // launch 2: split x
    split_bf_kernel<<<(NN * 128 + 255) / 256, 256>>>(x, xh, xl, NN * 128);
    // launch 3: gate gemm (N=128, gemm6)
    gemm6<EP_GATE, true, false, false><<<dim3(1, gy), 128, SMEM2>>>(
        xh, xl, wfah, wfal, fa_b, x, nullptr, gxh, gxl, nullptr, NN, 128, 128);
    // launch 4: layer-1 GEMM (N=512, gemm6 HB16)  <-- profiled launch
    gemm6<EP_NONE, false, true, true><<<dim3(4, gy), 128, SMEM2>>>(
        gxh, gxl, wb1h, wb1l, bb1, nullptr, res, nullptr, nullptr, hb, NN, 128, 512);

    // CSR build + head constants
    zero_kernel<<<nbN, TB>>>();
    deg_kernel<<<nbE, TB>>>(dst, ea);
    alloc_kernel<<<(NN + 1023) / 1024, 1024>>>();
    csr_kernel<<<nbE, TB>>>(dst, src, ea);
    ch123_kernel<<<1, 32>>>(We1, ae1, We2, ae2, We3, ae3);

    // remaining weight packs
    packfuseT_kernel<<<(512 * 256 + 255) / 256, 256>>>(r2_w, W2, wb2h, wb2l, 256, 256);
    packT_kernel<<<(64 * 256 + 255) / 256, 256>>>(W3, w3h, w3l, 256, 64);
    packT_kernel<<<(64 * 128 + 255) / 256, 256>>>(ffn_w1, wf1h, wf1l, 128, 64);
    packT_kernel<<<(64 * 64 + 255) / 256, 256>>>(ffn_w2, wf2h, wf2l, 64, 64);

    // ffn path (N=64 -> gemm5)
    gemm5<EP_RELU, true, false><<<dim3(1, gy), 256, SMEM_DB>>>(
        gxh, gxl, wf1h, wf1l, ffn_b1, nullptr, nullptr, t64h, t64l, NN, 128, 64);
    gemm5<EP_NONE, false, true><<<dim3(1, gy), 256, SMEM_DB>>>(
        t64h, t64l, wf2h, wf2l, ffn_b2, nullptr, zself, nullptr, nullptr, NN, 64, 64);

    // layer 1 attention + aggregation (bf16 h)
    attn_kernel<4, bf16><<<(NN * 4 * 32 + TB - 1) / TB, TB>>>(hb, 256, as1, ad1);
    agg4<4, 64, true, false, bf16><<<NN, 256>>>(hb, 256, b1, 0, res, 256,
                                                nullptr, z1h, z1l);

    // layer 2 (gemm6 HB16)
    gemm6<EP_NONE, false, true, true><<<dim3(4, gy), 128, SMEM2>>>(
        z1h, z1l, wb2h, wb2l, bb2, nullptr, res, nullptr, nullptr, hb, NN, 256, 512);
    attn_kernel<4, bf16><<<(NN * 4 * 32 + TB - 1) / TB, TB>>>(hb, 256, as2, ad2);
    agg4<4, 64, true, false, bf16><<<NN, 256>>>(hb, 256, b2, 4, res, 256,
                                                nullptr, z2h, z2l);

    // layer 3 (N=64 -> gemm5, fp32 path)
    gemm5<EP_NONE, false, true><<<dim3(1, gy), 256, SMEM_DB>>>(
        z2h, z2l, w3h, w3l, nullptr, nullptr, h3, nullptr, nullptr, NN, 256, 64);
    attn_kernel<1, float><<<(NN * 32 + TB - 1) / TB, TB>>>(h3, 64, as3, ad3);
    agg4<1, 64, false, true, float><<<NN, 64>>>(h3, 64, b3, 8, zself, 64,
                                                out, nullptr, nullptr);
}